// round 8
// baseline (speedup 1.0000x reference)
#include <cuda_runtime.h>
#include <cuda_fp16.h>
#include <math.h>
#include <cstdint>

// ---------------------------------------------------------------------------
// Problem constants: B=8, L=2048, D=1024, K=32, J=512
//   backbone0 n=2050, summarize n=514, backbone1 n=2082
//   Pad to NP=2176 (17*128) and NS=640 (5*128).
// ---------------------------------------------------------------------------
#define Bn 8
#define Dn 1024
#define NP 2176
#define NS 640

#define EL_XD ((size_t)Bn * NP * Dn)
#define EL_PP ((size_t)Bn * NP * NP)

__device__ __align__(256) __half g_X[EL_XD];
__device__ __align__(256) __half g_Q[EL_XD];
__device__ __align__(256) __half g_K[EL_XD];
__device__ __align__(256) __half g_Vt[EL_XD];   // V transposed [d][token]
__device__ __align__(256) __half g_O[EL_XD];
__device__ __align__(256) __half g_P[EL_PP];
__device__ __align__(256) float  g_S[EL_PP];
__device__ __align__(256) float  g_H[EL_XD];
__device__ __align__(256) __half g_WqT[Dn*Dn], g_WkT[Dn*Dn], g_WvT[Dn*Dn], g_WoT[Dn*Dn];
// stage C fp32 scratch
__device__ __align__(256) float g_M1[128 * Dn];
__device__ __align__(256) float g_S1[128 * Dn];
__device__ __align__(256) float g_Qn[128 * Dn];
__device__ __align__(256) float g_Kp[128 * Dn];
__device__ __align__(256) float g_P1[Bn * Dn];

// ---------------------------------------------------------------------------
// helpers
// ---------------------------------------------------------------------------
__device__ __forceinline__ uint32_t smem_u32(const void* p) {
    uint32_t a;
    asm("{ .reg .u64 t; cvta.to.shared.u64 t, %1; cvt.u32.u64 %0, t; }"
        : "=r"(a) : "l"(p));
    return a;
}
// SW128 swizzle for [row][64 half] tiles (128B rows): 16B chunk col XOR row%8
__device__ __forceinline__ uint32_t swz(int row, int col16) {
    return ((uint32_t)row << 7) | ((uint32_t)((col16 ^ row) & 7) << 4);
}
__device__ __forceinline__ void ldsm4(uint32_t* r, uint32_t addr) {
    asm volatile("ldmatrix.sync.aligned.m8n8.x4.shared.b16 {%0,%1,%2,%3}, [%4];"
        : "=r"(r[0]), "=r"(r[1]), "=r"(r[2]), "=r"(r[3]) : "r"(addr));
}
__device__ __forceinline__ void mma_f16(float* d, const uint32_t* a, const uint32_t* b) {
    asm volatile(
        "mma.sync.aligned.m16n8k16.row.col.f32.f16.f16.f32 "
        "{%0,%1,%2,%3}, {%4,%5,%6,%7}, {%8,%9}, {%0,%1,%2,%3};"
        : "+f"(d[0]), "+f"(d[1]), "+f"(d[2]), "+f"(d[3])
        : "r"(a[0]), "r"(a[1]), "r"(a[2]), "r"(a[3]), "r"(b[0]), "r"(b[1]));
}

// ---------------------------------------------------------------------------
// fp16 tensor-core GEMM: C = scale * A * B^T (+bias over cols)
//   CTA tile 256x128 (raises MAC/byte 1.33x -> under the ~6.3 KB/cyc LTS cap),
//   warp tile 64x64 (8 warps 4x2), K-chunk 64, 3-stage cp.async ring (144KB),
//   M-clamped loads + predicated stores (Mrows need not be a 256 multiple).
//   Kd = K extent (multiple of 64; may be < row stride to skip zero tail).
//   MODE 0: fp32 out; MODE 1: fp16 out; MODE 2: fp16 TRANSPOSED out.
//   Batched via blockIdx.z (element strides sA, sB, sC).
// ---------------------------------------------------------------------------
#define STAGE_B 49152            // A tile 32KB + B tile 16KB
#define TG_SMEM (3 * STAGE_B)    // 147456 bytes

__device__ __forceinline__ void fill_chunk(uint32_t sm,
    const __half* A, const __half* Bm, int ldA, int ldB, int mcap, int t, int c)
{
    long long k0 = (long long)c << 6;
    // A: 256 rows x 64 halfs (rows >= mcap clamped to mcap-1; outputs masked)
#pragma unroll
    for (int i = 0; i < 8; i++) {
        int seg = t + (i << 8);          // 0..2047 = row*8 + chunk
        int row = seg >> 3;
        int cc  = seg & 7;
        int rowc = row < mcap ? row : mcap - 1;
        asm volatile("cp.async.cg.shared.global [%0], [%1], 16;"
                     :: "r"(sm + swz(row, cc)),
                        "l"(A + (long long)rowc * ldA + k0 + ((long long)cc << 3)));
    }
    // B: 128 rows x 64 halfs
#pragma unroll
    for (int i = 0; i < 4; i++) {
        int seg = t + (i << 8);          // 0..1023
        int row = seg >> 3;
        int cc  = seg & 7;
        asm volatile("cp.async.cg.shared.global [%0], [%1], 16;"
                     :: "r"(sm + 32768u + swz(row, cc)),
                        "l"(Bm + (long long)row * ldB + k0 + ((long long)cc << 3)));
    }
}

template <int MODE, bool BIAS>
__global__ void __launch_bounds__(256, 1)
tgemm(const __half* __restrict__ A, const __half* __restrict__ Bm,
      float* __restrict__ Cf, __half* __restrict__ Ch,
      const float* __restrict__ bias,
      int Kd, int ldA, int ldB, int ldc, int Mrows, float scale,
      long long sA, long long sB, long long sC)
{
    extern __shared__ __align__(1024) char smem[];
    const int tid = threadIdx.x, wid = tid >> 5, lane = tid & 31;
    const long long z = blockIdx.z;
    A += z * sA; Bm += z * sB;
    if (MODE == 0) Cf += z * sC; else Ch += z * sC;

    const uint32_t sb = smem_u32(smem);
    const int row0 = blockIdx.y * 256;
    const int mcap = (Mrows - row0 < 256) ? (Mrows - row0) : 256;
    const __half* At = A  + (long long)row0 * ldA;
    const __half* Bt = Bm + (long long)blockIdx.x * 128 * ldB;

    const int wr = wid >> 1, wc = wid & 1;    // 4 x 2 warp grid, 64x64 tiles
    const int m0 = wr * 64, n0 = wc * 64;

    float acc[4][8][4];
#pragma unroll
    for (int i = 0; i < 4; i++)
#pragma unroll
        for (int j = 0; j < 8; j++)
#pragma unroll
            for (int r = 0; r < 4; r++) acc[i][j][r] = 0.f;

    const int NC = Kd >> 6;
    fill_chunk(sb, At, Bt, ldA, ldB, mcap, tid, 0);
    asm volatile("cp.async.commit_group;");
    if (NC > 1) {
        fill_chunk(sb + STAGE_B, At, Bt, ldA, ldB, mcap, tid, 1);
        asm volatile("cp.async.commit_group;");
    }

#pragma unroll 1
    for (int c = 0; c < NC; c++) {
        if (c == NC - 1) asm volatile("cp.async.wait_group 0;");
        else             asm volatile("cp.async.wait_group 1;");
        __syncthreads();

        const uint32_t tb = sb + (uint32_t)(c % 3) * STAGE_B;
        const uint32_t aA = tb, aB = tb + 32768u;

#pragma unroll
        for (int kk = 0; kk < 4; kk++) {
            const int k16 = kk << 1;  // 16B-chunk base of this 16-K step
            uint32_t Af[4][4], Bf[4][4];
            const int ar = m0 + (lane & 15);
            const int ac = k16 + (lane >> 4);
#pragma unroll
            for (int i = 0; i < 4; i++)
                ldsm4(Af[i], aA + swz(ar + 16 * i, ac));
            const int br = n0 + ((lane >> 4) << 3) + (lane & 7);
            const int bc = k16 + ((lane >> 3) & 1);
#pragma unroll
            for (int j2 = 0; j2 < 4; j2++)
                ldsm4(Bf[j2], aB + swz(br + 16 * j2, bc));
#pragma unroll
            for (int i = 0; i < 4; i++)
#pragma unroll
                for (int jt = 0; jt < 8; jt++)
                    mma_f16(acc[i][jt], Af[i], &Bf[jt >> 1][(jt & 1) << 1]);
        }
        if (c + 2 < NC) {
            fill_chunk(sb + (uint32_t)((c + 2) % 3) * STAGE_B, At, Bt, ldA, ldB,
                       mcap, tid, c + 2);
            asm volatile("cp.async.commit_group;");
        }
    }

    // ---------------- epilogue (rows >= mcap masked) ----------------
    const int col0 = blockIdx.x * 128;
    const int rl = lane >> 2;              // 0..7
    const int cl = (lane & 3) << 1;        // 0,2,4,6
#pragma unroll
    for (int i = 0; i < 4; i++) {
        const int r_in0 = m0 + i * 16 + rl;
        const int r_in1 = r_in0 + 8;
        const bool ok0 = r_in0 < mcap, ok1 = r_in1 < mcap;
        const long long rg0 = row0 + r_in0;
        const long long rg1 = row0 + r_in1;
#pragma unroll
        for (int j = 0; j < 8; j++) {
            const int cg = col0 + n0 + j * 8 + cl;
            float v00 = acc[i][j][0] * scale, v01 = acc[i][j][1] * scale;
            float v10 = acc[i][j][2] * scale, v11 = acc[i][j][3] * scale;
            if (BIAS) {
                const float b0 = bias[cg], b1 = bias[cg + 1];
                v00 += b0; v01 += b1; v10 += b0; v11 += b1;
            }
            if (MODE == 0) {
                if (ok0) *(float2*)(Cf + rg0 * ldc + cg) = make_float2(v00, v01);
                if (ok1) *(float2*)(Cf + rg1 * ldc + cg) = make_float2(v10, v11);
            } else if (MODE == 1) {
                if (ok0) *(__half2*)(Ch + rg0 * ldc + cg) =
                    __halves2half2(__float2half_rn(v00), __float2half_rn(v01));
                if (ok1) *(__half2*)(Ch + rg1 * ldc + cg) =
                    __halves2half2(__float2half_rn(v10), __float2half_rn(v11));
            } else {
                if (ok0) {
                    Ch[(long long)cg * ldc + rg0]       = __float2half_rn(v00);
                    Ch[(long long)(cg + 1) * ldc + rg0] = __float2half_rn(v01);
                }
                if (ok1) {
                    Ch[(long long)cg * ldc + rg1]       = __float2half_rn(v10);
                    Ch[(long long)(cg + 1) * ldc + rg1] = __float2half_rn(v11);
                }
            }
        }
    }
}

// ---------------------------------------------------------------------------
// Register-cached row softmax: ONE read of S, one exp, one fp16 write.
// ---------------------------------------------------------------------------
__global__ void softmax_reg(const float* __restrict__ S, __half* __restrict__ P,
                            int n, int npad)
{
    const long long roff = ((long long)blockIdx.y * npad + blockIdx.x) * npad;
    const float4* row4 = (const float4*)(S + roff);
    __half* pr = P + roff;
    const int t = threadIdx.x;
    const int npad4 = npad >> 2;
    __shared__ float red[256];

    float4 v[3];
    float m = -1e30f;
#pragma unroll
    for (int p = 0; p < 3; p++) {
        const int i4 = t + (p << 8);
        if (i4 < npad4) {
            v[p] = row4[i4];
            const int j = i4 << 2;
            if (j + 0 < n) m = fmaxf(m, v[p].x);
            if (j + 1 < n) m = fmaxf(m, v[p].y);
            if (j + 2 < n) m = fmaxf(m, v[p].z);
            if (j + 3 < n) m = fmaxf(m, v[p].w);
        }
    }
    red[t] = m; __syncthreads();
    for (int s = 128; s > 0; s >>= 1) {
        if (t < s) red[t] = fmaxf(red[t], red[t + s]);
        __syncthreads();
    }
    m = red[0]; __syncthreads();

    float sum = 0.f;
#pragma unroll
    for (int p = 0; p < 3; p++) {
        const int i4 = t + (p << 8);
        if (i4 < npad4) {
            const int j = i4 << 2;
            v[p].x = (j + 0 < n) ? __expf(v[p].x - m) : 0.f;
            v[p].y = (j + 1 < n) ? __expf(v[p].y - m) : 0.f;
            v[p].z = (j + 2 < n) ? __expf(v[p].z - m) : 0.f;
            v[p].w = (j + 3 < n) ? __expf(v[p].w - m) : 0.f;
            sum += v[p].x + v[p].y + v[p].z + v[p].w;
        }
    }
    red[t] = sum; __syncthreads();
    for (int s = 128; s > 0; s >>= 1) {
        if (t < s) red[t] += red[t + s];
        __syncthreads();
    }
    const float inv = 1.f / red[0];

#pragma unroll
    for (int p = 0; p < 3; p++) {
        const int i4 = t + (p << 8);
        if (i4 < npad4) {
            const int j = i4 << 2;
            *(__half2*)(pr + j)     = __halves2half2(__float2half_rn(v[p].x * inv),
                                                     __float2half_rn(v[p].y * inv));
            *(__half2*)(pr + j + 2) = __halves2half2(__float2half_rn(v[p].z * inv),
                                                     __float2half_rn(v[p].w * inv));
        }
    }
}

// ---------------------------------------------------------------------------
// Input assembly (fp32 -> fp16), 2 elems/thread (half2 stores)
// ---------------------------------------------------------------------------
__global__ void build_x0h(const float* __restrict__ seg0, __half* __restrict__ X)
{
    int b = blockIdx.y;
    long long i2 = (long long)blockIdx.x * 256 + threadIdx.x;   // over NP*Dn/2
    int pos = (int)(i2 >> 9), d = (int)((i2 & 511) << 1);
    float2 v = make_float2(0.f, 0.f);
    if (pos >= 1 && pos <= 2048)
        v = *(const float2*)(seg0 + ((long long)b * 2048 + (pos - 1)) * 1024 + d);
    *(__half2*)(X + (long long)b * NP * 1024 + (i2 << 1)) =
        __halves2half2(__float2half_rn(v.x), __float2half_rn(v.y));
}

__global__ void build_xsh(const float* __restrict__ seg1, const float* __restrict__ pe,
                          __half* __restrict__ X)
{
    int b = blockIdx.y;
    long long i2 = (long long)blockIdx.x * 256 + threadIdx.x;   // over NS*Dn/2
    int pos = (int)(i2 >> 9), d = (int)((i2 & 511) << 1);
    float2 v = make_float2(0.f, 0.f);
    if (pos == 0 || pos == 513) v = *(const float2*)(pe + d);
    else if (pos >= 1 && pos <= 512)
        v = *(const float2*)(seg1 + ((long long)b * 2048 + (pos - 1)) * 1024 + d);
    *(__half2*)(X + (long long)b * NS * 1024 + (i2 << 1)) =
        __halves2half2(__float2half_rn(v.x), __float2half_rn(v.y));
}

__global__ void build_x1h(const float* __restrict__ seg0, const float* __restrict__ seg1,
                          const float* __restrict__ P1, __half* __restrict__ X)
{
    int b = blockIdx.y;
    long long i2 = (long long)blockIdx.x * 256 + threadIdx.x;   // over NP*Dn/2
    int pos = (int)(i2 >> 9), d = (int)((i2 & 511) << 1);
    float2 v = make_float2(0.f, 0.f);
    if (pos < 32)
        v = *(const float2*)(seg0 + ((long long)b * 2048 + (2016 + pos)) * 1024 + d);
    else if (pos == 32 || pos == 2081)
        v = *(const float2*)(P1 + b * 1024 + d);
    else if (pos >= 33 && pos <= 2080)
        v = *(const float2*)(seg1 + ((long long)b * 2048 + (pos - 33)) * 1024 + d);
    *(__half2*)(X + (long long)b * NP * 1024 + (i2 << 1)) =
        __halves2half2(__float2half_rn(v.x), __float2half_rn(v.y));
}

// smem-tiled weight transpose + convert: WT[n][k] = half(W[k][n])
__global__ void wcvt_t(const float* __restrict__ W, __half* __restrict__ WT)
{
    __shared__ float tile[32][33];
    const int k0 = blockIdx.y * 32, n0 = blockIdx.x * 32;
    for (int r = threadIdx.y; r < 32; r += 8)
        tile[r][threadIdx.x] = W[(long long)(k0 + r) * 1024 + n0 + threadIdx.x];
    __syncthreads();
    for (int r = threadIdx.y; r < 32; r += 8)
        WT[(long long)(n0 + r) * 1024 + k0 + threadIdx.x] =
            __float2half_rn(tile[threadIdx.x][r]);
}

// copy tokens [33, 33+tokens) of H (stride npad) into output region, float4
__global__ void copy_out(const float* __restrict__ H, float* __restrict__ out,
                         int tokens, int npad, long long off)
{
    int b = blockIdx.y;
    long long i4 = (long long)blockIdx.x * 256 + threadIdx.x;  // over tokens*1024/4
    *(float4*)(out + off + (long long)b * tokens * 1024 + (i4 << 2)) =
        *(const float4*)(H + (long long)b * npad * 1024 + 33LL * 1024 + (i4 << 2));
}

__global__ void copy_pad128(const float* __restrict__ H, float* __restrict__ dst,
                            int npad, int token)
{
    long long i = (long long)blockIdx.x * 256 + threadIdx.x;
    int r = (int)(i >> 10), d = (int)(i & 1023);
    dst[i] = (r < Bn) ? H[((long long)r * npad + token) * 1024 + d] : 0.f;
}

// ---------------------------------------------------------------------------
// fp32 fallback SGEMM (stage C only; tiny)
// ---------------------------------------------------------------------------
template <bool TRANSB, bool BIAS>
__global__ void __launch_bounds__(256)
sgemm(const float* __restrict__ A, const float* __restrict__ Bm,
      float* __restrict__ C, const float* __restrict__ bias,
      int N, int Kd, float scale)
{
    __shared__ float As[8][128];
    __shared__ float Bs[8][128];
    const int t = threadIdx.x, tx = t & 15, ty = t >> 4;
    const int row0 = blockIdx.y * 128, col0 = blockIdx.x * 128;
    const int aRow = t >> 1, aCol = (t & 1) << 2;
    const int bRow = t >> 5, bCol = (t & 31) << 2;
    float acc[8][8];
#pragma unroll
    for (int i = 0; i < 8; i++)
#pragma unroll
        for (int j = 0; j < 8; j++) acc[i][j] = 0.f;
    const float* Aptr = A + (long long)(row0 + aRow) * Kd + aCol;
    const float* Bptr = TRANSB ? (Bm + (long long)(col0 + aRow) * Kd + aCol)
                               : (Bm + (long long)bRow * N + col0 + bCol);
    for (int k0 = 0; k0 < Kd; k0 += 8) {
        float4 av = *(const float4*)(Aptr + k0);
        As[aCol + 0][aRow] = av.x; As[aCol + 1][aRow] = av.y;
        As[aCol + 2][aRow] = av.z; As[aCol + 3][aRow] = av.w;
        if (TRANSB) {
            float4 bv = *(const float4*)(Bptr + k0);
            Bs[aCol + 0][aRow] = bv.x; Bs[aCol + 1][aRow] = bv.y;
            Bs[aCol + 2][aRow] = bv.z; Bs[aCol + 3][aRow] = bv.w;
        } else {
            float4 bv = *(const float4*)(Bptr + (long long)k0 * N);
            *(float4*)&Bs[bRow][bCol] = bv;
        }
        __syncthreads();
#pragma unroll
        for (int kk = 0; kk < 8; kk++) {
            float ar[8], br[8];
            *(float4*)&ar[0] = *(const float4*)&As[kk][ty * 8];
            *(float4*)&ar[4] = *(const float4*)&As[kk][ty * 8 + 4];
            *(float4*)&br[0] = *(const float4*)&Bs[kk][tx * 8];
            *(float4*)&br[4] = *(const float4*)&Bs[kk][tx * 8 + 4];
#pragma unroll
            for (int i = 0; i < 8; i++)
#pragma unroll
                for (int j = 0; j < 8; j++)
                    acc[i][j] = fmaf(ar[i], br[j], acc[i][j]);
        }
        __syncthreads();
    }
#pragma unroll
    for (int i = 0; i < 8; i++) {
        long long r = row0 + ty * 8 + i;
#pragma unroll
        for (int j = 0; j < 8; j += 4) {
            int c = col0 + tx * 8 + j;
            float4 v;
            v.x = acc[i][j + 0] * scale; v.y = acc[i][j + 1] * scale;
            v.z = acc[i][j + 2] * scale; v.w = acc[i][j + 3] * scale;
            if (BIAS) { v.x += bias[c]; v.y += bias[c + 1]; v.z += bias[c + 2]; v.w += bias[c + 3]; }
            *(float4*)(C + r * N + c) = v;
        }
    }
}

// Tiny 8-way memory attention
__global__ void mem_attn(const float* __restrict__ Qn, const float* __restrict__ Kp,
                         const float* __restrict__ M1, float* __restrict__ P1)
{
    int b = blockIdx.x, t = threadIdx.x;
    __shared__ float red[256];
    __shared__ float attn[Bn];
    for (int j = 0; j < Bn; j++) {
        float p = 0.f;
        for (int d = t; d < 1024; d += 256)
            p += Qn[b * 1024 + d] * Kp[j * 1024 + d];
        red[t] = p; __syncthreads();
        for (int s = 128; s > 0; s >>= 1) {
            if (t < s) red[t] += red[t + s];
            __syncthreads();
        }
        if (t == 0) attn[j] = red[0] * 0.03125f;
        __syncthreads();
    }
    if (t == 0) {
        float m = -1e30f;
        for (int j = 0; j < Bn; j++) m = fmaxf(m, attn[j]);
        float s = 0.f;
        for (int j = 0; j < Bn; j++) { attn[j] = __expf(attn[j] - m); s += attn[j]; }
        float inv = 1.f / s;
        for (int j = 0; j < Bn; j++) attn[j] *= inv;
    }
    __syncthreads();
    for (int d = t; d < 1024; d += 256) {
        float v = 0.f;
#pragma unroll
        for (int j = 0; j < Bn; j++) v += attn[j] * M1[j * 1024 + d];
        P1[b * 1024 + d] = v;
    }
}

// ---------------------------------------------------------------------------
// Host orchestration
// ---------------------------------------------------------------------------
struct Ptrs {
    __half *X, *Q, *K, *Vt, *O, *P;
    __half *WqT, *WkT, *WvT, *WoT;
    float *S, *H, *M1, *S1, *Qn, *Kp, *P1;
};

static void run_backbone_tc(const Ptrs& p,
                            const float* bq, const float* bk,
                            const float* bv, const float* bo,
                            int n, int npad)
{
    const int mt = npad / 128;               // N col tiles (128 wide)
    const int gy = (npad + 255) / 256;       // M row tiles (256 tall, clamped)
    const long long sXD = (long long)npad * Dn;
    const long long sPP = (long long)npad * npad;
    const int KT = ((n + 63) / 64) * 64;     // PV K-extent (P cols >= n are zero)
    dim3 gp(Dn / 128, gy, Bn);
    // projections
    tgemm<1, true><<<gp, 256, TG_SMEM>>>(p.X, p.WqT, nullptr, p.Q, bq,
        Dn, Dn, Dn, Dn, npad, 1.f, sXD, 0, sXD);
    tgemm<1, true><<<gp, 256, TG_SMEM>>>(p.X, p.WkT, nullptr, p.K, bk,
        Dn, Dn, Dn, Dn, npad, 1.f, sXD, 0, sXD);
    tgemm<2, true><<<gp, 256, TG_SMEM>>>(p.X, p.WvT, nullptr, p.Vt, bv,
        Dn, Dn, Dn, npad, npad, 1.f, sXD, 0, sXD);
    // scores
    dim3 gs(mt, gy, Bn);
    tgemm<0, false><<<gs, 256, TG_SMEM>>>(p.Q, p.K, p.S, nullptr, nullptr,
        Dn, Dn, Dn, npad, npad, 0.03125f, sXD, sXD, sPP);
    softmax_reg<<<dim3(n, Bn), 256>>>(p.S, p.P, n, npad);
    // attn @ V  (K-extent truncated to KT)
    tgemm<1, false><<<gp, 256, TG_SMEM>>>(p.P, p.Vt, nullptr, p.O, nullptr,
        KT, npad, npad, Dn, npad, 1.f, sPP, sXD, sXD);
    // output proj
    tgemm<0, true><<<gp, 256, TG_SMEM>>>(p.O, p.WoT, p.H, nullptr, bo,
        Dn, Dn, Dn, Dn, npad, 1.f, sXD, 0, sXD);
}

extern "C" void kernel_launch(void* const* d_in, const int* in_sizes, int n_in,
                              void* d_out, int out_size)
{
    const float* seg0   = (const float*)d_in[0];
    const float* seg1   = (const float*)d_in[1];
    const float* pe     = (const float*)d_in[2];
    const float* Wq_mem = (const float*)d_in[3];
    const float* bq_mem = (const float*)d_in[4];
    const float* Wk_mem = (const float*)d_in[5];
    const float* bk_mem = (const float*)d_in[6];
    const float* Wq     = (const float*)d_in[7];
    const float* bq     = (const float*)d_in[8];
    const float* Wk     = (const float*)d_in[9];
    const float* bk     = (const float*)d_in[10];
    const float* Wv     = (const float*)d_in[11];
    const float* bv     = (const float*)d_in[12];
    const float* Wo     = (const float*)d_in[13];
    const float* bo     = (const float*)d_in[14];
    float* out = (float*)d_out;

    cudaFuncSetAttribute(tgemm<0, false>, cudaFuncAttributeMaxDynamicSharedMemorySize, TG_SMEM);
    cudaFuncSetAttribute(tgemm<0, true>,  cudaFuncAttributeMaxDynamicSharedMemorySize, TG_SMEM);
    cudaFuncSetAttribute(tgemm<1, false>, cudaFuncAttributeMaxDynamicSharedMemorySize, TG_SMEM);
    cudaFuncSetAttribute(tgemm<1, true>,  cudaFuncAttributeMaxDynamicSharedMemorySize, TG_SMEM);
    cudaFuncSetAttribute(tgemm<2, true>,  cudaFuncAttributeMaxDynamicSharedMemorySize, TG_SMEM);

    Ptrs p;
    cudaGetSymbolAddress((void**)&p.X, g_X);
    cudaGetSymbolAddress((void**)&p.Q, g_Q);
    cudaGetSymbolAddress((void**)&p.K, g_K);
    cudaGetSymbolAddress((void**)&p.Vt, g_Vt);
    cudaGetSymbolAddress((void**)&p.O, g_O);
    cudaGetSymbolAddress((void**)&p.P, g_P);
    cudaGetSymbolAddress((void**)&p.WqT, g_WqT);
    cudaGetSymbolAddress((void**)&p.WkT, g_WkT);
    cudaGetSymbolAddress((void**)&p.WvT, g_WvT);
    cudaGetSymbolAddress((void**)&p.WoT, g_WoT);
    cudaGetSymbolAddress((void**)&p.S, g_S);
    cudaGetSymbolAddress((void**)&p.H, g_H);
    cudaGetSymbolAddress((void**)&p.M1, g_M1);
    cudaGetSymbolAddress((void**)&p.S1, g_S1);
    cudaGetSymbolAddress((void**)&p.Qn, g_Qn);
    cudaGetSymbolAddress((void**)&p.Kp, g_Kp);
    cudaGetSymbolAddress((void**)&p.P1, g_P1);

    dim3 wg(32, 32), wb(32, 8);
    wcvt_t<<<wg, wb>>>(Wq, p.WqT);
    wcvt_t<<<wg, wb>>>(Wk, p.WkT);
    wcvt_t<<<wg, wb>>>(Wv, p.WvT);
    wcvt_t<<<wg, wb>>>(Wo, p.WoT);

    // ---- Stage A: backbone over input_h0 (n = 2050) ----
    build_x0h<<<dim3(NP * Dn / 512, Bn), 256>>>(seg0, p.X);
    run_backbone_tc(p, bq, bk, bv, bo, 2050, NP);
    copy_out<<<dim3(2016 * Dn / 1024, Bn), 256>>>(p.H, out, 2016, NP, 0LL);
    copy_pad128<<<dim3(128 * Dn / 256), 256>>>(p.H, p.M1, NP, 2049);

    // ---- Stage B: summarize(seg1) (n = 514) ----
    build_xsh<<<dim3(NS * Dn / 512, Bn), 256>>>(seg1, pe, p.X);
    run_backbone_tc(p, bq, bk, bv, bo, 514, NS);
    copy_pad128<<<dim3(128 * Dn / 256), 256>>>(p.H, p.S1, NS, 512);

    // ---- Stage C: memory attention (tiny, fp32 path) ----
    dim3 gMem(Dn / 128, 1, 1);
    sgemm<false, true><<<gMem, 256>>>(p.S1, Wq_mem, p.Qn, bq_mem, Dn, Dn, 1.f);
    sgemm<false, true><<<gMem, 256>>>(p.M1, Wk_mem, p.Kp, bk_mem, Dn, Dn, 1.f);
    mem_attn<<<Bn, 256>>>(p.Qn, p.Kp, p.M1, p.P1);

    // ---- Stage D: backbone over input_h1 (n = 2082) ----
    build_x1h<<<dim3(NP * Dn / 512, Bn), 256>>>(seg0, seg1, p.P1, p.X);
    run_backbone_tc(p, bq, bk, bv, bo, 2082, NP);
    copy_out<<<dim3(2048 * Dn / 1024, Bn), 256>>>(p.H, out, 2048, NP,
                                                  (long long)Bn * 2016 * Dn);
}

// round 9
// speedup vs baseline: 1.1008x; 1.1008x over previous
#include <cuda_runtime.h>
#include <cuda_fp16.h>
#include <math.h>
#include <cstdint>

// ---------------------------------------------------------------------------
// Problem constants: B=8, L=2048, D=1024, K=32, J=512
//   backbone0 n=2050, summarize n=514, backbone1 n=2082
//   Pad to NP=2176 (17*128) and NS=640 (5*128).
// ---------------------------------------------------------------------------
#define Bn 8
#define Dn 1024
#define NP 2176
#define NS 640

#define EL_XD ((size_t)Bn * NP * Dn)
#define EL_PP ((size_t)Bn * NP * NP)

__device__ __align__(256) __half g_X[EL_XD];
__device__ __align__(256) __half g_Q[EL_XD];
__device__ __align__(256) __half g_K[EL_XD];
__device__ __align__(256) __half g_Vt[EL_XD];   // V transposed [d][token]
__device__ __align__(256) __half g_O[EL_XD];
__device__ __align__(256) __half g_P[EL_PP];
__device__ __align__(256) float  g_S[EL_PP];
__device__ __align__(256) __half g_WqT[Dn*Dn], g_WkT[Dn*Dn], g_WvT[Dn*Dn], g_WoT[Dn*Dn];
// stage C fp32 scratch. g_M1/g_S1 rows 8..127 are NEVER written -> stay at
// their zero initialization (device .bss), giving the zero-padded 128-row
// operands stage C's sgemm expects.
__device__ __align__(256) float g_M1[128 * Dn];
__device__ __align__(256) float g_S1[128 * Dn];
__device__ __align__(256) float g_Qn[128 * Dn];
__device__ __align__(256) float g_Kp[128 * Dn];
__device__ __align__(256) float g_P1[Bn * Dn];

// ---------------------------------------------------------------------------
// helpers
// ---------------------------------------------------------------------------
__device__ __forceinline__ uint32_t smem_u32(const void* p) {
    uint32_t a;
    asm("{ .reg .u64 t; cvta.to.shared.u64 t, %1; cvt.u32.u64 %0, t; }"
        : "=r"(a) : "l"(p));
    return a;
}
// SW128 swizzle for [row][64 half] tiles (128B rows): 16B chunk col XOR row%8
__device__ __forceinline__ uint32_t swz(int row, int col16) {
    return ((uint32_t)row << 7) | ((uint32_t)((col16 ^ row) & 7) << 4);
}
__device__ __forceinline__ void ldsm4(uint32_t* r, uint32_t addr) {
    asm volatile("ldmatrix.sync.aligned.m8n8.x4.shared.b16 {%0,%1,%2,%3}, [%4];"
        : "=r"(r[0]), "=r"(r[1]), "=r"(r[2]), "=r"(r[3]) : "r"(addr));
}
__device__ __forceinline__ void mma_f16(float* d, const uint32_t* a, const uint32_t* b) {
    asm volatile(
        "mma.sync.aligned.m16n8k16.row.col.f32.f16.f16.f32 "
        "{%0,%1,%2,%3}, {%4,%5,%6,%7}, {%8,%9}, {%0,%1,%2,%3};"
        : "+f"(d[0]), "+f"(d[1]), "+f"(d[2]), "+f"(d[3])
        : "r"(a[0]), "r"(a[1]), "r"(a[2]), "r"(a[3]), "r"(b[0]), "r"(b[1]));
}

// ---------------------------------------------------------------------------
// fp16 tensor-core GEMM: C = scale * A * B^T (+bias over cols)
//   A: [M][>=Kd] fp16, row stride ldA; B: [N][>=Kd] fp16, row stride ldB.
//   Kd = K extent (multiple of 64; may be < row stride to skip zero tail).
//   CTA tile 128x128, warp tile 64x32 (8 warps 2x4), K-chunk 64,
//   3-stage cp.async ring, fp32 accum (HMMA half-rate is the roofline here).
//   MODE 0: fp32 out
//   MODE 1: fp16 out
//   MODE 2: fp16 TRANSPOSED out
//   MODE 3: fused fp32 output epilogue — local row r writes:
//             r in [33, 33+tokens)  -> Cf[z*sC + (r-33)*ldc + col]
//             r == mtok             -> aux[z*1024 + col]
//           (all other rows discarded; removes the H buffer + copy kernels)
//   Batched via blockIdx.z (element strides sA, sB, sC).
// ---------------------------------------------------------------------------
#define STAGE_B 32768            // A tile 16KB + B tile 16KB
#define TG_SMEM (3 * STAGE_B)    // 98304 bytes

__device__ __forceinline__ void fill_chunk(uint32_t sm,
    const __half* A, const __half* Bm, int ldA, int ldB, int t, int c)
{
    long long k0 = (long long)c << 6;
#pragma unroll
    for (int i = 0; i < 4; i++) {
        int seg = t + (i << 8);          // 0..1023 = row*8 + chunk
        int row = seg >> 3;
        int cc  = seg & 7;
        uint32_t so = swz(row, cc);
        asm volatile("cp.async.cg.shared.global [%0], [%1], 16;"
                     :: "r"(sm + so),
                        "l"(A + (long long)row * ldA + k0 + ((long long)cc << 3)));
        asm volatile("cp.async.cg.shared.global [%0], [%1], 16;"
                     :: "r"(sm + 16384u + so),
                        "l"(Bm + (long long)row * ldB + k0 + ((long long)cc << 3)));
    }
}

template <int MODE, bool BIAS>
__global__ void __launch_bounds__(256, 2)
tgemm(const __half* __restrict__ A, const __half* __restrict__ Bm,
      float* __restrict__ Cf, __half* __restrict__ Ch,
      const float* __restrict__ bias, float* __restrict__ aux,
      int tokens, int mtok,
      int Kd, int ldA, int ldB, int ldc, float scale,
      long long sA, long long sB, long long sC)
{
    extern __shared__ __align__(1024) char smem[];
    const int tid = threadIdx.x, wid = tid >> 5, lane = tid & 31;
    const long long z = blockIdx.z;
    A += z * sA; Bm += z * sB;
    if (MODE == 0 || MODE == 3) Cf += z * sC; else Ch += z * sC;

    const uint32_t sb = smem_u32(smem);
    const __half* At = A  + (long long)blockIdx.y * 128 * ldA;
    const __half* Bt = Bm + (long long)blockIdx.x * 128 * ldB;

    const int wr = wid >> 2, wc = wid & 3;    // 2 x 4 warp grid
    const int m0 = wr * 64, n0 = wc * 32;

    float acc[4][4][4];
#pragma unroll
    for (int i = 0; i < 4; i++)
#pragma unroll
        for (int j = 0; j < 4; j++)
#pragma unroll
            for (int r = 0; r < 4; r++) acc[i][j][r] = 0.f;

    const int NC = Kd >> 6;
    fill_chunk(sb, At, Bt, ldA, ldB, tid, 0);
    asm volatile("cp.async.commit_group;");
    if (NC > 1) {
        fill_chunk(sb + STAGE_B, At, Bt, ldA, ldB, tid, 1);
        asm volatile("cp.async.commit_group;");
    }

#pragma unroll 1
    for (int c = 0; c < NC; c++) {
        if (c == NC - 1) asm volatile("cp.async.wait_group 0;");
        else             asm volatile("cp.async.wait_group 1;");
        __syncthreads();

        const uint32_t tb = sb + (uint32_t)(c % 3) * STAGE_B;
        const uint32_t aA = tb, aB = tb + 16384u;

#pragma unroll
        for (int kk = 0; kk < 4; kk++) {
            const int k16 = kk << 1;  // 16B-chunk base of this 16-K step
            uint32_t Af[4][4], Bf[2][4];
            const int ar = m0 + (lane & 15);
            const int ac = k16 + (lane >> 4);
#pragma unroll
            for (int i = 0; i < 4; i++)
                ldsm4(Af[i], aA + swz(ar + 16 * i, ac));
            const int br = n0 + ((lane >> 4) << 3) + (lane & 7);
            const int bc = k16 + ((lane >> 3) & 1);
#pragma unroll
            for (int j2 = 0; j2 < 2; j2++)
                ldsm4(Bf[j2], aB + swz(br + 16 * j2, bc));
#pragma unroll
            for (int i = 0; i < 4; i++)
#pragma unroll
                for (int jt = 0; jt < 4; jt++)
                    mma_f16(acc[i][jt], Af[i], &Bf[jt >> 1][(jt & 1) << 1]);
        }
        if (c + 2 < NC) {
            fill_chunk(sb + (uint32_t)((c + 2) % 3) * STAGE_B, At, Bt, ldA, ldB,
                       tid, c + 2);
            asm volatile("cp.async.commit_group;");
        }
    }

    // ---------------- epilogue ----------------
    const int row0 = blockIdx.y * 128, col0 = blockIdx.x * 128;
    const int rl = lane >> 2;              // 0..7
    const int cl = (lane & 3) << 1;        // 0,2,4,6
#pragma unroll
    for (int i = 0; i < 4; i++) {
        const long long rg0 = row0 + m0 + i * 16 + rl;
        const long long rg1 = rg0 + 8;
#pragma unroll
        for (int j = 0; j < 4; j++) {
            const int cg = col0 + n0 + j * 8 + cl;
            float v00 = acc[i][j][0] * scale, v01 = acc[i][j][1] * scale;
            float v10 = acc[i][j][2] * scale, v11 = acc[i][j][3] * scale;
            if (BIAS) {
                const float b0 = bias[cg], b1 = bias[cg + 1];
                v00 += b0; v01 += b1; v10 += b0; v11 += b1;
            }
            if (MODE == 0) {
                *(float2*)(Cf + rg0 * ldc + cg) = make_float2(v00, v01);
                *(float2*)(Cf + rg1 * ldc + cg) = make_float2(v10, v11);
            } else if (MODE == 1) {
                *(__half2*)(Ch + rg0 * ldc + cg) =
                    __halves2half2(__float2half_rn(v00), __float2half_rn(v01));
                *(__half2*)(Ch + rg1 * ldc + cg) =
                    __halves2half2(__float2half_rn(v10), __float2half_rn(v11));
            } else if (MODE == 2) {
                Ch[(long long)cg * ldc + rg0]       = __float2half_rn(v00);
                Ch[(long long)(cg + 1) * ldc + rg0] = __float2half_rn(v01);
                Ch[(long long)cg * ldc + rg1]       = __float2half_rn(v10);
                Ch[(long long)(cg + 1) * ldc + rg1] = __float2half_rn(v11);
            } else {
                const int r0 = (int)rg0, r1 = (int)rg1;
                if (r0 >= 33 && r0 < 33 + tokens)
                    *(float2*)(Cf + (long long)(r0 - 33) * ldc + cg) =
                        make_float2(v00, v01);
                if (r0 == mtok)
                    *(float2*)(aux + z * 1024 + cg) = make_float2(v00, v01);
                if (r1 >= 33 && r1 < 33 + tokens)
                    *(float2*)(Cf + (long long)(r1 - 33) * ldc + cg) =
                        make_float2(v10, v11);
                if (r1 == mtok)
                    *(float2*)(aux + z * 1024 + cg) = make_float2(v10, v11);
            }
        }
    }
}

// ---------------------------------------------------------------------------
// Register-cached row softmax: ONE read of S, one exp, one fp16 write.
// Processes rows [row0, row0 + gridDim.x); cols >= n written as 0.
// ---------------------------------------------------------------------------
__global__ void softmax_reg(const float* __restrict__ S, __half* __restrict__ P,
                            int n, int npad, int row0)
{
    const long long roff =
        ((long long)blockIdx.y * npad + (row0 + blockIdx.x)) * npad;
    const float4* row4 = (const float4*)(S + roff);
    __half* pr = P + roff;
    const int t = threadIdx.x;
    const int npad4 = npad >> 2;
    __shared__ float red[256];

    float4 v[3];
    float m = -1e30f;
#pragma unroll
    for (int p = 0; p < 3; p++) {
        const int i4 = t + (p << 8);
        if (i4 < npad4) {
            v[p] = row4[i4];
            const int j = i4 << 2;
            if (j + 0 < n) m = fmaxf(m, v[p].x);
            if (j + 1 < n) m = fmaxf(m, v[p].y);
            if (j + 2 < n) m = fmaxf(m, v[p].z);
            if (j + 3 < n) m = fmaxf(m, v[p].w);
        }
    }
    red[t] = m; __syncthreads();
    for (int s = 128; s > 0; s >>= 1) {
        if (t < s) red[t] = fmaxf(red[t], red[t + s]);
        __syncthreads();
    }
    m = red[0]; __syncthreads();

    float sum = 0.f;
#pragma unroll
    for (int p = 0; p < 3; p++) {
        const int i4 = t + (p << 8);
        if (i4 < npad4) {
            const int j = i4 << 2;
            v[p].x = (j + 0 < n) ? __expf(v[p].x - m) : 0.f;
            v[p].y = (j + 1 < n) ? __expf(v[p].y - m) : 0.f;
            v[p].z = (j + 2 < n) ? __expf(v[p].z - m) : 0.f;
            v[p].w = (j + 3 < n) ? __expf(v[p].w - m) : 0.f;
            sum += v[p].x + v[p].y + v[p].z + v[p].w;
        }
    }
    red[t] = sum; __syncthreads();
    for (int s = 128; s > 0; s >>= 1) {
        if (t < s) red[t] += red[t + s];
        __syncthreads();
    }
    const float inv = 1.f / red[0];

#pragma unroll
    for (int p = 0; p < 3; p++) {
        const int i4 = t + (p << 8);
        if (i4 < npad4) {
            const int j = i4 << 2;
            *(__half2*)(pr + j)     = __halves2half2(__float2half_rn(v[p].x * inv),
                                                     __float2half_rn(v[p].y * inv));
            *(__half2*)(pr + j + 2) = __halves2half2(__float2half_rn(v[p].z * inv),
                                                     __float2half_rn(v[p].w * inv));
        }
    }
}

// ---------------------------------------------------------------------------
// Input assembly (fp32 -> fp16), 2 elems/thread (half2 stores)
// ---------------------------------------------------------------------------
__global__ void build_x0h(const float* __restrict__ seg0, __half* __restrict__ X)
{
    int b = blockIdx.y;
    long long i2 = (long long)blockIdx.x * 256 + threadIdx.x;   // over NP*Dn/2
    int pos = (int)(i2 >> 9), d = (int)((i2 & 511) << 1);
    float2 v = make_float2(0.f, 0.f);
    if (pos >= 1 && pos <= 2048)
        v = *(const float2*)(seg0 + ((long long)b * 2048 + (pos - 1)) * 1024 + d);
    *(__half2*)(X + (long long)b * NP * 1024 + (i2 << 1)) =
        __halves2half2(__float2half_rn(v.x), __float2half_rn(v.y));
}

__global__ void build_xsh(const float* __restrict__ seg1, const float* __restrict__ pe,
                          __half* __restrict__ X)
{
    int b = blockIdx.y;
    long long i2 = (long long)blockIdx.x * 256 + threadIdx.x;   // over NS*Dn/2
    int pos = (int)(i2 >> 9), d = (int)((i2 & 511) << 1);
    float2 v = make_float2(0.f, 0.f);
    if (pos == 0 || pos == 513) v = *(const float2*)(pe + d);
    else if (pos >= 1 && pos <= 512)
        v = *(const float2*)(seg1 + ((long long)b * 2048 + (pos - 1)) * 1024 + d);
    *(__half2*)(X + (long long)b * NS * 1024 + (i2 << 1)) =
        __halves2half2(__float2half_rn(v.x), __float2half_rn(v.y));
}

__global__ void build_x1h(const float* __restrict__ seg0, const float* __restrict__ seg1,
                          const float* __restrict__ P1, __half* __restrict__ X)
{
    int b = blockIdx.y;
    long long i2 = (long long)blockIdx.x * 256 + threadIdx.x;   // over NP*Dn/2
    int pos = (int)(i2 >> 9), d = (int)((i2 & 511) << 1);
    float2 v = make_float2(0.f, 0.f);
    if (pos < 32)
        v = *(const float2*)(seg0 + ((long long)b * 2048 + (2016 + pos)) * 1024 + d);
    else if (pos == 32 || pos == 2081)
        v = *(const float2*)(P1 + b * 1024 + d);
    else if (pos >= 33 && pos <= 2080)
        v = *(const float2*)(seg1 + ((long long)b * 2048 + (pos - 33)) * 1024 + d);
    *(__half2*)(X + (long long)b * NP * 1024 + (i2 << 1)) =
        __halves2half2(__float2half_rn(v.x), __float2half_rn(v.y));
}

// smem-tiled weight transpose + convert: WT[n][k] = half(W[k][n])
__global__ void wcvt_t(const float* __restrict__ W, __half* __restrict__ WT)
{
    __shared__ float tile[32][33];
    const int k0 = blockIdx.y * 32, n0 = blockIdx.x * 32;
    for (int r = threadIdx.y; r < 32; r += 8)
        tile[r][threadIdx.x] = W[(long long)(k0 + r) * 1024 + n0 + threadIdx.x];
    __syncthreads();
    for (int r = threadIdx.y; r < 32; r += 8)
        WT[(long long)(n0 + r) * 1024 + k0 + threadIdx.x] =
            __float2half_rn(tile[threadIdx.x][r]);
}

// ---------------------------------------------------------------------------
// fp32 fallback SGEMM (stage C only; tiny)
// ---------------------------------------------------------------------------
template <bool TRANSB, bool BIAS>
__global__ void __launch_bounds__(256)
sgemm(const float* __restrict__ A, const float* __restrict__ Bm,
      float* __restrict__ C, const float* __restrict__ bias,
      int N, int Kd, float scale)
{
    __shared__ float As[8][128];
    __shared__ float Bs[8][128];
    const int t = threadIdx.x, tx = t & 15, ty = t >> 4;
    const int row0 = blockIdx.y * 128, col0 = blockIdx.x * 128;
    const int aRow = t >> 1, aCol = (t & 1) << 2;
    const int bRow = t >> 5, bCol = (t & 31) << 2;
    float acc[8][8];
#pragma unroll
    for (int i = 0; i < 8; i++)
#pragma unroll
        for (int j = 0; j < 8; j++) acc[i][j] = 0.f;
    const float* Aptr = A + (long long)(row0 + aRow) * Kd + aCol;
    const float* Bptr = TRANSB ? (Bm + (long long)(col0 + aRow) * Kd + aCol)
                               : (Bm + (long long)bRow * N + col0 + bCol);
    for (int k0 = 0; k0 < Kd; k0 += 8) {
        float4 av = *(const float4*)(Aptr + k0);
        As[aCol + 0][aRow] = av.x; As[aCol + 1][aRow] = av.y;
        As[aCol + 2][aRow] = av.z; As[aCol + 3][aRow] = av.w;
        if (TRANSB) {
            float4 bv = *(const float4*)(Bptr + k0);
            Bs[aCol + 0][aRow] = bv.x; Bs[aCol + 1][aRow] = bv.y;
            Bs[aCol + 2][aRow] = bv.z; Bs[aCol + 3][aRow] = bv.w;
        } else {
            float4 bv = *(const float4*)(Bptr + (long long)k0 * N);
            *(float4*)&Bs[bRow][bCol] = bv;
        }
        __syncthreads();
#pragma unroll
        for (int kk = 0; kk < 8; kk++) {
            float ar[8], br[8];
            *(float4*)&ar[0] = *(const float4*)&As[kk][ty * 8];
            *(float4*)&ar[4] = *(const float4*)&As[kk][ty * 8 + 4];
            *(float4*)&br[0] = *(const float4*)&Bs[kk][tx * 8];
            *(float4*)&br[4] = *(const float4*)&Bs[kk][tx * 8 + 4];
#pragma unroll
            for (int i = 0; i < 8; i++)
#pragma unroll
                for (int j = 0; j < 8; j++)
                    acc[i][j] = fmaf(ar[i], br[j], acc[i][j]);
        }
        __syncthreads();
    }
#pragma unroll
    for (int i = 0; i < 8; i++) {
        long long r = row0 + ty * 8 + i;
#pragma unroll
        for (int j = 0; j < 8; j += 4) {
            int c = col0 + tx * 8 + j;
            float4 v;
            v.x = acc[i][j + 0] * scale; v.y = acc[i][j + 1] * scale;
            v.z = acc[i][j + 2] * scale; v.w = acc[i][j + 3] * scale;
            if (BIAS) { v.x += bias[c]; v.y += bias[c + 1]; v.z += bias[c + 2]; v.w += bias[c + 3]; }
            *(float4*)(C + r * N + c) = v;
        }
    }
}

// Tiny 8-way memory attention
__global__ void mem_attn(const float* __restrict__ Qn, const float* __restrict__ Kp,
                         const float* __restrict__ M1, float* __restrict__ P1)
{
    int b = blockIdx.x, t = threadIdx.x;
    __shared__ float red[256];
    __shared__ float attn[Bn];
    for (int j = 0; j < Bn; j++) {
        float p = 0.f;
        for (int d = t; d < 1024; d += 256)
            p += Qn[b * 1024 + d] * Kp[j * 1024 + d];
        red[t] = p; __syncthreads();
        for (int s = 128; s > 0; s >>= 1) {
            if (t < s) red[t] += red[t + s];
            __syncthreads();
        }
        if (t == 0) attn[j] = red[0] * 0.03125f;
        __syncthreads();
    }
    if (t == 0) {
        float m = -1e30f;
        for (int j = 0; j < Bn; j++) m = fmaxf(m, attn[j]);
        float s = 0.f;
        for (int j = 0; j < Bn; j++) { attn[j] = __expf(attn[j] - m); s += attn[j]; }
        float inv = 1.f / s;
        for (int j = 0; j < Bn; j++) attn[j] *= inv;
    }
    __syncthreads();
    for (int d = t; d < 1024; d += 256) {
        float v = 0.f;
#pragma unroll
        for (int j = 0; j < Bn; j++) v += attn[j] * M1[j * 1024 + d];
        P1[b * 1024 + d] = v;
    }
}

// ---------------------------------------------------------------------------
// Host orchestration
// ---------------------------------------------------------------------------
struct Ptrs {
    __half *X, *Q, *K, *Vt, *O, *P;
    __half *WqT, *WkT, *WvT, *WoT;
    float *S, *M1, *S1, *Qn, *Kp, *P1;
};

// Full backbone (stages A/D, npad = NP): O-proj writes `outp` (row-33 remap)
// and the summary token `mtok` into `aux` directly.
static void run_backbone_full(const Ptrs& p,
                              const float* bq, const float* bk,
                              const float* bv, const float* bo,
                              int n, float* outp, int tokens, int mtok,
                              float* aux)
{
    const int mt = NP / 128;
    const long long sXD = (long long)NP * Dn;
    const long long sPP = (long long)NP * NP;
    const int KT = ((n + 63) / 64) * 64;
    dim3 gp(Dn / 128, mt, Bn);
    tgemm<1, true><<<gp, 256, TG_SMEM>>>(p.X, p.WqT, nullptr, p.Q, bq,
        nullptr, 0, -1, Dn, Dn, Dn, Dn, 1.f, sXD, 0, sXD);
    tgemm<1, true><<<gp, 256, TG_SMEM>>>(p.X, p.WkT, nullptr, p.K, bk,
        nullptr, 0, -1, Dn, Dn, Dn, Dn, 1.f, sXD, 0, sXD);
    tgemm<2, true><<<gp, 256, TG_SMEM>>>(p.X, p.WvT, nullptr, p.Vt, bv,
        nullptr, 0, -1, Dn, Dn, Dn, NP, 1.f, sXD, 0, sXD);
    dim3 gs(mt, mt, Bn);
    tgemm<0, false><<<gs, 256, TG_SMEM>>>(p.Q, p.K, p.S, nullptr, nullptr,
        nullptr, 0, -1, Dn, Dn, Dn, NP, 0.03125f, sXD, sXD, sPP);
    softmax_reg<<<dim3(n, Bn), 256>>>(p.S, p.P, n, NP, 0);
    tgemm<1, false><<<gp, 256, TG_SMEM>>>(p.P, p.Vt, nullptr, p.O, nullptr,
        nullptr, 0, -1, KT, NP, NP, Dn, 1.f, sPP, sXD, sXD);
    // fused output projection
    tgemm<3, true><<<gp, 256, TG_SMEM>>>(p.O, p.WoT, outp, nullptr, bo,
        aux, tokens, mtok, Dn, Dn, Dn, Dn, 1.f, sXD, 0,
        (long long)tokens * Dn);
}

extern "C" void kernel_launch(void* const* d_in, const int* in_sizes, int n_in,
                              void* d_out, int out_size)
{
    const float* seg0   = (const float*)d_in[0];
    const float* seg1   = (const float*)d_in[1];
    const float* pe     = (const float*)d_in[2];
    const float* Wq_mem = (const float*)d_in[3];
    const float* bq_mem = (const float*)d_in[4];
    const float* Wk_mem = (const float*)d_in[5];
    const float* bk_mem = (const float*)d_in[6];
    const float* Wq     = (const float*)d_in[7];
    const float* bq     = (const float*)d_in[8];
    const float* Wk     = (const float*)d_in[9];
    const float* bk     = (const float*)d_in[10];
    const float* Wv     = (const float*)d_in[11];
    const float* bv     = (const float*)d_in[12];
    const float* Wo     = (const float*)d_in[13];
    const float* bo     = (const float*)d_in[14];
    float* out = (float*)d_out;

    cudaFuncSetAttribute(tgemm<0, false>, cudaFuncAttributeMaxDynamicSharedMemorySize, TG_SMEM);
    cudaFuncSetAttribute(tgemm<1, false>, cudaFuncAttributeMaxDynamicSharedMemorySize, TG_SMEM);
    cudaFuncSetAttribute(tgemm<1, true>,  cudaFuncAttributeMaxDynamicSharedMemorySize, TG_SMEM);
    cudaFuncSetAttribute(tgemm<2, true>,  cudaFuncAttributeMaxDynamicSharedMemorySize, TG_SMEM);
    cudaFuncSetAttribute(tgemm<3, true>,  cudaFuncAttributeMaxDynamicSharedMemorySize, TG_SMEM);

    Ptrs p;
    cudaGetSymbolAddress((void**)&p.X, g_X);
    cudaGetSymbolAddress((void**)&p.Q, g_Q);
    cudaGetSymbolAddress((void**)&p.K, g_K);
    cudaGetSymbolAddress((void**)&p.Vt, g_Vt);
    cudaGetSymbolAddress((void**)&p.O, g_O);
    cudaGetSymbolAddress((void**)&p.P, g_P);
    cudaGetSymbolAddress((void**)&p.WqT, g_WqT);
    cudaGetSymbolAddress((void**)&p.WkT, g_WkT);
    cudaGetSymbolAddress((void**)&p.WvT, g_WvT);
    cudaGetSymbolAddress((void**)&p.WoT, g_WoT);
    cudaGetSymbolAddress((void**)&p.S, g_S);
    cudaGetSymbolAddress((void**)&p.M1, g_M1);
    cudaGetSymbolAddress((void**)&p.S1, g_S1);
    cudaGetSymbolAddress((void**)&p.Qn, g_Qn);
    cudaGetSymbolAddress((void**)&p.Kp, g_Kp);
    cudaGetSymbolAddress((void**)&p.P1, g_P1);

    dim3 wg(32, 32), wb(32, 8);
    wcvt_t<<<wg, wb>>>(Wq, p.WqT);
    wcvt_t<<<wg, wb>>>(Wk, p.WkT);
    wcvt_t<<<wg, wb>>>(Wv, p.WvT);
    wcvt_t<<<wg, wb>>>(Wo, p.WoT);

    // ---- Stage A: backbone over input_h0 (n = 2050) ----
    // out0 = rows 33..2048 (2016 tokens) written directly; M1 = row 2049.
    build_x0h<<<dim3(NP * Dn / 512, Bn), 256>>>(seg0, p.X);
    run_backbone_full(p, bq, bk, bv, bo, 2050, out, 2016, 2049, p.M1);

    // ---- Stage B: summarize(seg1) (n = 514) ----
    // Only output token 512 is needed -> Q-proj/scores/softmax/PV/O-proj all
    // run on the single 128-row M-tile [512, 640) via pointer offsets.
    {
        const long long sXD = (long long)NS * Dn;
        const long long sPP = (long long)NS * NS;
        build_xsh<<<dim3(NS * Dn / 512, Bn), 256>>>(seg1, pe, p.X);
        // K and V projections over the full sequence (keys/values)
        tgemm<1, true><<<dim3(8, 5, Bn), 256, TG_SMEM>>>(p.X, p.WkT, nullptr,
            p.K, bk, nullptr, 0, -1, Dn, Dn, Dn, Dn, 1.f, sXD, 0, sXD);
        tgemm<2, true><<<dim3(8, 5, Bn), 256, TG_SMEM>>>(p.X, p.WvT, nullptr,
            p.Vt, bv, nullptr, 0, -1, Dn, Dn, Dn, NS, 1.f, sXD, 0, sXD);
        // Q projection: only rows 512..639
        tgemm<1, true><<<dim3(8, 1, Bn), 256, TG_SMEM>>>(p.X + 512 * Dn, p.WqT,
            nullptr, p.Q + 512 * Dn, bq, nullptr, 0, -1,
            Dn, Dn, Dn, Dn, 1.f, sXD, 0, sXD);
        // scores: rows 512..639 x all keys
        tgemm<0, false><<<dim3(5, 1, Bn), 256, TG_SMEM>>>(p.Q + 512 * Dn, p.K,
            p.S + 512 * NS, nullptr, nullptr, nullptr, 0, -1,
            Dn, Dn, Dn, NS, 0.03125f, sXD, sXD, sPP);
        // softmax over rows 512..639 (sanitizes the whole tile; n = 514)
        softmax_reg<<<dim3(128, Bn), 256>>>(p.S, p.P, 514, NS, 512);
        // PV: rows 512..639, K extent 576 (P cols >= 514 are zero)
        tgemm<1, false><<<dim3(8, 1, Bn), 256, TG_SMEM>>>(p.P + 512 * NS, p.Vt,
            nullptr, p.O + 512 * Dn, nullptr, nullptr, 0, -1,
            576, NS, NS, Dn, 1.f, sPP, sXD, sXD);
        // O-proj: local row 0 (= token 512) -> S1; no out writes (tokens=0)
        tgemm<3, true><<<dim3(8, 1, Bn), 256, TG_SMEM>>>(p.O + 512 * Dn, p.WoT,
            out, nullptr, bo, p.S1, 0, 0, Dn, Dn, Dn, Dn, 1.f, sXD, 0, 0);
    }

    // ---- Stage C: memory attention (tiny, fp32 path) ----
    dim3 gMem(Dn / 128, 1, 1);
    sgemm<false, true><<<gMem, 256>>>(p.S1, Wq_mem, p.Qn, bq_mem, Dn, Dn, 1.f);
    sgemm<false, true><<<gMem, 256>>>(p.M1, Wk_mem, p.Kp, bk_mem, Dn, Dn, 1.f);
    mem_attn<<<Bn, 256>>>(p.Qn, p.Kp, p.M1, p.P1);

    // ---- Stage D: backbone over input_h1 (n = 2082) ----
    // out1 = rows 33..2080 (2048 tokens); no summary token.
    build_x1h<<<dim3(NP * Dn / 512, Bn), 256>>>(seg0, seg1, p.P1, p.X);
    run_backbone_full(p, bq, bk, bv, bo, 2082,
                      out + (long long)Bn * 2016 * Dn, 2048, -1, p.M1);
}

// round 10
// speedup vs baseline: 1.1596x; 1.0534x over previous
#include <cuda_runtime.h>
#include <cuda_fp16.h>
#include <math.h>
#include <cstdint>

// ---------------------------------------------------------------------------
// Problem constants: B=8, L=2048, D=1024, K=32, J=512
//   backbone0 n=2050, summarize n=514, backbone1 n=2082
//   Pad to NP=2176 (17*128) and NS=640 (5*128).
//   Stages A/D: query rows are processed offset by 33 -> exactly 2048 rows
//   (16 M-tiles) cover every needed output token; K/V keep all 17 tiles.
// ---------------------------------------------------------------------------
#define Bn 8
#define Dn 1024
#define NP 2176
#define NS 640
#define MQ 2048   // query rows per batch in stages A/D (local row = global-33)

#define EL_XD ((size_t)Bn * NP * Dn)
#define EL_PP ((size_t)Bn * NP * NP)

__device__ __align__(256) __half g_X[EL_XD];
__device__ __align__(256) __half g_Q[EL_XD];
__device__ __align__(256) __half g_K[EL_XD];
__device__ __align__(256) __half g_Vt[EL_XD];   // V transposed [d][token]
__device__ __align__(256) __half g_O[EL_XD];
__device__ __align__(256) __half g_P[EL_PP];
__device__ __align__(256) float  g_S[EL_PP];
__device__ __align__(256) __half g_WqT[Dn*Dn], g_WkT[Dn*Dn], g_WvT[Dn*Dn], g_WoT[Dn*Dn];
// stage C fp32 scratch. g_M1/g_S1 rows 8..127 are NEVER written -> stay at
// their zero initialization (device .bss), giving the zero-padded 128-row
// operands stage C's sgemm expects.
__device__ __align__(256) float g_M1[128 * Dn];
__device__ __align__(256) float g_S1[128 * Dn];
__device__ __align__(256) float g_Qn[128 * Dn];
__device__ __align__(256) float g_Kp[128 * Dn];
__device__ __align__(256) float g_P1[Bn * Dn];

// ---------------------------------------------------------------------------
// helpers
// ---------------------------------------------------------------------------
__device__ __forceinline__ uint32_t smem_u32(const void* p) {
    uint32_t a;
    asm("{ .reg .u64 t; cvta.to.shared.u64 t, %1; cvt.u32.u64 %0, t; }"
        : "=r"(a) : "l"(p));
    return a;
}
// SW128 swizzle for [row][64 half] tiles (128B rows): 16B chunk col XOR row%8
__device__ __forceinline__ uint32_t swz(int row, int col16) {
    return ((uint32_t)row << 7) | ((uint32_t)((col16 ^ row) & 7) << 4);
}
__device__ __forceinline__ void ldsm4(uint32_t* r, uint32_t addr) {
    asm volatile("ldmatrix.sync.aligned.m8n8.x4.shared.b16 {%0,%1,%2,%3}, [%4];"
        : "=r"(r[0]), "=r"(r[1]), "=r"(r[2]), "=r"(r[3]) : "r"(addr));
}
__device__ __forceinline__ void mma_f16(float* d, const uint32_t* a, const uint32_t* b) {
    asm volatile(
        "mma.sync.aligned.m16n8k16.row.col.f32.f16.f16.f32 "
        "{%0,%1,%2,%3}, {%4,%5,%6,%7}, {%8,%9}, {%0,%1,%2,%3};"
        : "+f"(d[0]), "+f"(d[1]), "+f"(d[2]), "+f"(d[3])
        : "r"(a[0]), "r"(a[1]), "r"(a[2]), "r"(a[3]), "r"(b[0]), "r"(b[1]));
}

// ---------------------------------------------------------------------------
// fp16 tensor-core GEMM: C = scale * A * B^T (+bias over cols)
//   A: [M][>=Kd] fp16, row stride ldA; B: [N][>=Kd] fp16, row stride ldB.
//   Kd = K extent (multiple of 64; may be < row stride to skip zero tail).
//   CTA tile 128x128, warp tile 64x32 (8 warps 2x4), K-chunk 64,
//   3-stage cp.async ring, fp32 accum (HMMA half-rate is the roofline here).
//   MODE 0: fp32 out
//   MODE 1: fp16 out
//   MODE 2: fp16 TRANSPOSED out
//   MODE 3: fused fp32 output epilogue — local row r writes:
//             r < tokens  -> Cf[z*sC + r*ldc + col]
//             r == mtok   -> aux[z*1024 + col]
//           (other rows discarded)
//   Batched via blockIdx.z (element strides sA, sB, sC).
// ---------------------------------------------------------------------------
#define STAGE_B 32768            // A tile 16KB + B tile 16KB
#define TG_SMEM (3 * STAGE_B)    // 98304 bytes

__device__ __forceinline__ void fill_chunk(uint32_t sm,
    const __half* A, const __half* Bm, int ldA, int ldB, int t, int c)
{
    long long k0 = (long long)c << 6;
#pragma unroll
    for (int i = 0; i < 4; i++) {
        int seg = t + (i << 8);          // 0..1023 = row*8 + chunk
        int row = seg >> 3;
        int cc  = seg & 7;
        uint32_t so = swz(row, cc);
        asm volatile("cp.async.cg.shared.global [%0], [%1], 16;"
                     :: "r"(sm + so),
                        "l"(A + (long long)row * ldA + k0 + ((long long)cc << 3)));
        asm volatile("cp.async.cg.shared.global [%0], [%1], 16;"
                     :: "r"(sm + 16384u + so),
                        "l"(Bm + (long long)row * ldB + k0 + ((long long)cc << 3)));
    }
}

template <int MODE, bool BIAS>
__global__ void __launch_bounds__(256, 2)
tgemm(const __half* __restrict__ A, const __half* __restrict__ Bm,
      float* __restrict__ Cf, __half* __restrict__ Ch,
      const float* __restrict__ bias, float* __restrict__ aux,
      int tokens, int mtok,
      int Kd, int ldA, int ldB, int ldc, float scale,
      long long sA, long long sB, long long sC)
{
    extern __shared__ __align__(1024) char smem[];
    const int tid = threadIdx.x, wid = tid >> 5, lane = tid & 31;
    const long long z = blockIdx.z;
    A += z * sA; Bm += z * sB;
    if (MODE == 0 || MODE == 3) Cf += z * sC; else Ch += z * sC;

    const uint32_t sb = smem_u32(smem);
    const __half* At = A  + (long long)blockIdx.y * 128 * ldA;
    const __half* Bt = Bm + (long long)blockIdx.x * 128 * ldB;

    const int wr = wid >> 2, wc = wid & 3;    // 2 x 4 warp grid
    const int m0 = wr * 64, n0 = wc * 32;

    float acc[4][4][4];
#pragma unroll
    for (int i = 0; i < 4; i++)
#pragma unroll
        for (int j = 0; j < 4; j++)
#pragma unroll
            for (int r = 0; r < 4; r++) acc[i][j][r] = 0.f;

    const int NC = Kd >> 6;
    fill_chunk(sb, At, Bt, ldA, ldB, tid, 0);
    asm volatile("cp.async.commit_group;");
    if (NC > 1) {
        fill_chunk(sb + STAGE_B, At, Bt, ldA, ldB, tid, 1);
        asm volatile("cp.async.commit_group;");
    }

#pragma unroll 1
    for (int c = 0; c < NC; c++) {
        if (c == NC - 1) asm volatile("cp.async.wait_group 0;");
        else             asm volatile("cp.async.wait_group 1;");
        __syncthreads();

        const uint32_t tb = sb + (uint32_t)(c % 3) * STAGE_B;
        const uint32_t aA = tb, aB = tb + 16384u;

#pragma unroll
        for (int kk = 0; kk < 4; kk++) {
            const int k16 = kk << 1;  // 16B-chunk base of this 16-K step
            uint32_t Af[4][4], Bf[2][4];
            const int ar = m0 + (lane & 15);
            const int ac = k16 + (lane >> 4);
#pragma unroll
            for (int i = 0; i < 4; i++)
                ldsm4(Af[i], aA + swz(ar + 16 * i, ac));
            const int br = n0 + ((lane >> 4) << 3) + (lane & 7);
            const int bc = k16 + ((lane >> 3) & 1);
#pragma unroll
            for (int j2 = 0; j2 < 2; j2++)
                ldsm4(Bf[j2], aB + swz(br + 16 * j2, bc));
#pragma unroll
            for (int i = 0; i < 4; i++)
#pragma unroll
                for (int jt = 0; jt < 4; jt++)
                    mma_f16(acc[i][jt], Af[i], &Bf[jt >> 1][(jt & 1) << 1]);
        }
        if (c + 2 < NC) {
            fill_chunk(sb + (uint32_t)((c + 2) % 3) * STAGE_B, At, Bt, ldA, ldB,
                       tid, c + 2);
            asm volatile("cp.async.commit_group;");
        }
    }

    // ---------------- epilogue ----------------
    const int row0 = blockIdx.y * 128, col0 = blockIdx.x * 128;
    const int rl = lane >> 2;              // 0..7
    const int cl = (lane & 3) << 1;        // 0,2,4,6
#pragma unroll
    for (int i = 0; i < 4; i++) {
        const long long rg0 = row0 + m0 + i * 16 + rl;
        const long long rg1 = rg0 + 8;
#pragma unroll
        for (int j = 0; j < 4; j++) {
            const int cg = col0 + n0 + j * 8 + cl;
            float v00 = acc[i][j][0] * scale, v01 = acc[i][j][1] * scale;
            float v10 = acc[i][j][2] * scale, v11 = acc[i][j][3] * scale;
            if (BIAS) {
                const float b0 = bias[cg], b1 = bias[cg + 1];
                v00 += b0; v01 += b1; v10 += b0; v11 += b1;
            }
            if (MODE == 0) {
                *(float2*)(Cf + rg0 * ldc + cg) = make_float2(v00, v01);
                *(float2*)(Cf + rg1 * ldc + cg) = make_float2(v10, v11);
            } else if (MODE == 1) {
                *(__half2*)(Ch + rg0 * ldc + cg) =
                    __halves2half2(__float2half_rn(v00), __float2half_rn(v01));
                *(__half2*)(Ch + rg1 * ldc + cg) =
                    __halves2half2(__float2half_rn(v10), __float2half_rn(v11));
            } else if (MODE == 2) {
                Ch[(long long)cg * ldc + rg0]       = __float2half_rn(v00);
                Ch[(long long)(cg + 1) * ldc + rg0] = __float2half_rn(v01);
                Ch[(long long)cg * ldc + rg1]       = __float2half_rn(v10);
                Ch[(long long)(cg + 1) * ldc + rg1] = __float2half_rn(v11);
            } else {
                const int r0 = (int)rg0, r1 = (int)rg1;
                if (r0 < tokens)
                    *(float2*)(Cf + (long long)r0 * ldc + cg) =
                        make_float2(v00, v01);
                if (r0 == mtok)
                    *(float2*)(aux + z * 1024 + cg) = make_float2(v00, v01);
                if (r1 < tokens)
                    *(float2*)(Cf + (long long)r1 * ldc + cg) =
                        make_float2(v10, v11);
                if (r1 == mtok)
                    *(float2*)(aux + z * 1024 + cg) = make_float2(v10, v11);
            }
        }
    }
}

// ---------------------------------------------------------------------------
// Register-cached row softmax: ONE read of S, one exp, one fp16 write.
// Batch b's rows live at (b*rowsPB + row)*npad. Processes rows
// [row0, row0 + gridDim.x); cols >= n written as 0.
// ---------------------------------------------------------------------------
__global__ void softmax_reg(const float* __restrict__ S, __half* __restrict__ P,
                            int n, int npad, int rowsPB, int row0)
{
    const long long roff =
        ((long long)blockIdx.y * rowsPB + (row0 + blockIdx.x)) * npad;
    const float4* row4 = (const float4*)(S + roff);
    __half* pr = P + roff;
    const int t = threadIdx.x;
    const int npad4 = npad >> 2;
    __shared__ float red[256];

    float4 v[3];
    float m = -1e30f;
#pragma unroll
    for (int p = 0; p < 3; p++) {
        const int i4 = t + (p << 8);
        if (i4 < npad4) {
            v[p] = row4[i4];
            const int j = i4 << 2;
            if (j + 0 < n) m = fmaxf(m, v[p].x);
            if (j + 1 < n) m = fmaxf(m, v[p].y);
            if (j + 2 < n) m = fmaxf(m, v[p].z);
            if (j + 3 < n) m = fmaxf(m, v[p].w);
        }
    }
    red[t] = m; __syncthreads();
    for (int s = 128; s > 0; s >>= 1) {
        if (t < s) red[t] = fmaxf(red[t], red[t + s]);
        __syncthreads();
    }
    m = red[0]; __syncthreads();

    float sum = 0.f;
#pragma unroll
    for (int p = 0; p < 3; p++) {
        const int i4 = t + (p << 8);
        if (i4 < npad4) {
            const int j = i4 << 2;
            v[p].x = (j + 0 < n) ? __expf(v[p].x - m) : 0.f;
            v[p].y = (j + 1 < n) ? __expf(v[p].y - m) : 0.f;
            v[p].z = (j + 2 < n) ? __expf(v[p].z - m) : 0.f;
            v[p].w = (j + 3 < n) ? __expf(v[p].w - m) : 0.f;
            sum += v[p].x + v[p].y + v[p].z + v[p].w;
        }
    }
    red[t] = sum; __syncthreads();
    for (int s = 128; s > 0; s >>= 1) {
        if (t < s) red[t] += red[t + s];
        __syncthreads();
    }
    const float inv = 1.f / red[0];

#pragma unroll
    for (int p = 0; p < 3; p++) {
        const int i4 = t + (p << 8);
        if (i4 < npad4) {
            const int j = i4 << 2;
            *(__half2*)(pr + j)     = __halves2half2(__float2half_rn(v[p].x * inv),
                                                     __float2half_rn(v[p].y * inv));
            *(__half2*)(pr + j + 2) = __halves2half2(__float2half_rn(v[p].z * inv),
                                                     __float2half_rn(v[p].w * inv));
        }
    }
}

// ---------------------------------------------------------------------------
// Input assembly (fp32 -> fp16), 2 elems/thread (half2 stores)
// ---------------------------------------------------------------------------
__global__ void build_x0h(const float* __restrict__ seg0, __half* __restrict__ X)
{
    int b = blockIdx.y;
    long long i2 = (long long)blockIdx.x * 256 + threadIdx.x;   // over NP*Dn/2
    int pos = (int)(i2 >> 9), d = (int)((i2 & 511) << 1);
    float2 v = make_float2(0.f, 0.f);
    if (pos >= 1 && pos <= 2048)
        v = *(const float2*)(seg0 + ((long long)b * 2048 + (pos - 1)) * 1024 + d);
    *(__half2*)(X + (long long)b * NP * 1024 + (i2 << 1)) =
        __halves2half2(__float2half_rn(v.x), __float2half_rn(v.y));
}

__global__ void build_xsh(const float* __restrict__ seg1, const float* __restrict__ pe,
                          __half* __restrict__ X)
{
    int b = blockIdx.y;
    long long i2 = (long long)blockIdx.x * 256 + threadIdx.x;   // over NS*Dn/2
    int pos = (int)(i2 >> 9), d = (int)((i2 & 511) << 1);
    float2 v = make_float2(0.f, 0.f);
    if (pos == 0 || pos == 513) v = *(const float2*)(pe + d);
    else if (pos >= 1 && pos <= 512)
        v = *(const float2*)(seg1 + ((long long)b * 2048 + (pos - 1)) * 1024 + d);
    *(__half2*)(X + (long long)b * NS * 1024 + (i2 << 1)) =
        __halves2half2(__float2half_rn(v.x), __float2half_rn(v.y));
}

__global__ void build_x1h(const float* __restrict__ seg0, const float* __restrict__ seg1,
                          const float* __restrict__ P1, __half* __restrict__ X)
{
    int b = blockIdx.y;
    long long i2 = (long long)blockIdx.x * 256 + threadIdx.x;   // over NP*Dn/2
    int pos = (int)(i2 >> 9), d = (int)((i2 & 511) << 1);
    float2 v = make_float2(0.f, 0.f);
    if (pos < 32)
        v = *(const float2*)(seg0 + ((long long)b * 2048 + (2016 + pos)) * 1024 + d);
    else if (pos == 32 || pos == 2081)
        v = *(const float2*)(P1 + b * 1024 + d);
    else if (pos >= 33 && pos <= 2080)
        v = *(const float2*)(seg1 + ((long long)b * 2048 + (pos - 33)) * 1024 + d);
    *(__half2*)(X + (long long)b * NP * 1024 + (i2 << 1)) =
        __halves2half2(__float2half_rn(v.x), __float2half_rn(v.y));
}

// smem-tiled weight transpose + convert: WT[n][k] = half(W[k][n])
__global__ void wcvt_t(const float* __restrict__ W, __half* __restrict__ WT)
{
    __shared__ float tile[32][33];
    const int k0 = blockIdx.y * 32, n0 = blockIdx.x * 32;
    for (int r = threadIdx.y; r < 32; r += 8)
        tile[r][threadIdx.x] = W[(long long)(k0 + r) * 1024 + n0 + threadIdx.x];
    __syncthreads();
    for (int r = threadIdx.y; r < 32; r += 8)
        WT[(long long)(n0 + r) * 1024 + k0 + threadIdx.x] =
            __float2half_rn(tile[threadIdx.x][r]);
}

// ---------------------------------------------------------------------------
// fp32 fallback SGEMM (stage C only; tiny)
// ---------------------------------------------------------------------------
template <bool TRANSB, bool BIAS>
__global__ void __launch_bounds__(256)
sgemm(const float* __restrict__ A, const float* __restrict__ Bm,
      float* __restrict__ C, const float* __restrict__ bias,
      int N, int Kd, float scale)
{
    __shared__ float As[8][128];
    __shared__ float Bs[8][128];
    const int t = threadIdx.x, tx = t & 15, ty = t >> 4;
    const int row0 = blockIdx.y * 128, col0 = blockIdx.x * 128;
    const int aRow = t >> 1, aCol = (t & 1) << 2;
    const int bRow = t >> 5, bCol = (t & 31) << 2;
    float acc[8][8];
#pragma unroll
    for (int i = 0; i < 8; i++)
#pragma unroll
        for (int j = 0; j < 8; j++) acc[i][j] = 0.f;
    const float* Aptr = A + (long long)(row0 + aRow) * Kd + aCol;
    const float* Bptr = TRANSB ? (Bm + (long long)(col0 + aRow) * Kd + aCol)
                               : (Bm + (long long)bRow * N + col0 + bCol);
    for (int k0 = 0; k0 < Kd; k0 += 8) {
        float4 av = *(const float4*)(Aptr + k0);
        As[aCol + 0][aRow] = av.x; As[aCol + 1][aRow] = av.y;
        As[aCol + 2][aRow] = av.z; As[aCol + 3][aRow] = av.w;
        if (TRANSB) {
            float4 bv = *(const float4*)(Bptr + k0);
            Bs[aCol + 0][aRow] = bv.x; Bs[aCol + 1][aRow] = bv.y;
            Bs[aCol + 2][aRow] = bv.z; Bs[aCol + 3][aRow] = bv.w;
        } else {
            float4 bv = *(const float4*)(Bptr + (long long)k0 * N);
            *(float4*)&Bs[bRow][bCol] = bv;
        }
        __syncthreads();
#pragma unroll
        for (int kk = 0; kk < 8; kk++) {
            float ar[8], br[8];
            *(float4*)&ar[0] = *(const float4*)&As[kk][ty * 8];
            *(float4*)&ar[4] = *(const float4*)&As[kk][ty * 8 + 4];
            *(float4*)&br[0] = *(const float4*)&Bs[kk][tx * 8];
            *(float4*)&br[4] = *(const float4*)&Bs[kk][tx * 8 + 4];
#pragma unroll
            for (int i = 0; i < 8; i++)
#pragma unroll
                for (int j = 0; j < 8; j++)
                    acc[i][j] = fmaf(ar[i], br[j], acc[i][j]);
        }
        __syncthreads();
    }
#pragma unroll
    for (int i = 0; i < 8; i++) {
        long long r = row0 + ty * 8 + i;
#pragma unroll
        for (int j = 0; j < 8; j += 4) {
            int c = col0 + tx * 8 + j;
            float4 v;
            v.x = acc[i][j + 0] * scale; v.y = acc[i][j + 1] * scale;
            v.z = acc[i][j + 2] * scale; v.w = acc[i][j + 3] * scale;
            if (BIAS) { v.x += bias[c]; v.y += bias[c + 1]; v.z += bias[c + 2]; v.w += bias[c + 3]; }
            *(float4*)(C + r * N + c) = v;
        }
    }
}

// Tiny 8-way memory attention
__global__ void mem_attn(const float* __restrict__ Qn, const float* __restrict__ Kp,
                         const float* __restrict__ M1, float* __restrict__ P1)
{
    int b = blockIdx.x, t = threadIdx.x;
    __shared__ float red[256];
    __shared__ float attn[Bn];
    for (int j = 0; j < Bn; j++) {
        float p = 0.f;
        for (int d = t; d < 1024; d += 256)
            p += Qn[b * 1024 + d] * Kp[j * 1024 + d];
        red[t] = p; __syncthreads();
        for (int s = 128; s > 0; s >>= 1) {
            if (t < s) red[t] += red[t + s];
            __syncthreads();
        }
        if (t == 0) attn[j] = red[0] * 0.03125f;
        __syncthreads();
    }
    if (t == 0) {
        float m = -1e30f;
        for (int j = 0; j < Bn; j++) m = fmaxf(m, attn[j]);
        float s = 0.f;
        for (int j = 0; j < Bn; j++) { attn[j] = __expf(attn[j] - m); s += attn[j]; }
        float inv = 1.f / s;
        for (int j = 0; j < Bn; j++) attn[j] *= inv;
    }
    __syncthreads();
    for (int d = t; d < 1024; d += 256) {
        float v = 0.f;
#pragma unroll
        for (int j = 0; j < Bn; j++) v += attn[j] * M1[j * 1024 + d];
        P1[b * 1024 + d] = v;
    }
}

// ---------------------------------------------------------------------------
// Host orchestration
// ---------------------------------------------------------------------------
struct Ptrs {
    __half *X, *Q, *K, *Vt, *O, *P;
    __half *WqT, *WkT, *WvT, *WoT;
    float *S, *M1, *S1, *Qn, *Kp, *P1;
};

// Full backbone (stages A/D). Query side runs on MQ=2048 rows = global rows
// [33, 2081) via a 33-row pointer offset: local row r == output token r.
// O-proj writes outp rows [0, tokens) and aux (summary) at local row mtok.
static void run_backbone_full(const Ptrs& p,
                              const float* bq, const float* bk,
                              const float* bv, const float* bo,
                              int n, float* outp, int tokens, int mtok,
                              float* aux)
{
    const long long sXD = (long long)NP * Dn;
    const long long sS  = (long long)MQ * NP;   // S/P per-batch stride
    const int KT = ((n + 63) / 64) * 64;
    // K/V projections: all 17 tiles (every key/value row)
    tgemm<1, true><<<dim3(8, 17, Bn), 256, TG_SMEM>>>(p.X, p.WkT, nullptr, p.K,
        bk, nullptr, 0, -1, Dn, Dn, Dn, Dn, 1.f, sXD, 0, sXD);
    tgemm<2, true><<<dim3(8, 17, Bn), 256, TG_SMEM>>>(p.X, p.WvT, nullptr, p.Vt,
        bv, nullptr, 0, -1, Dn, Dn, Dn, NP, 1.f, sXD, 0, sXD);
    // Q projection: 16 tiles, rows 33..2080
    tgemm<1, true><<<dim3(8, 16, Bn), 256, TG_SMEM>>>(p.X + 33 * Dn, p.WqT,
        nullptr, p.Q, bq, nullptr, 0, -1, Dn, Dn, Dn, Dn, 1.f, sXD, 0, sXD);
    // scores: 2048 query rows x 2176 key cols
    tgemm<0, false><<<dim3(17, 16, Bn), 256, TG_SMEM>>>(p.Q, p.K, p.S, nullptr,
        nullptr, nullptr, 0, -1, Dn, Dn, Dn, NP, 0.03125f, sXD, sXD, sS);
    softmax_reg<<<dim3(MQ, Bn), 256>>>(p.S, p.P, n, NP, MQ, 0);
    // attn @ V (K-extent truncated; P cols >= n are zero)
    tgemm<1, false><<<dim3(8, 16, Bn), 256, TG_SMEM>>>(p.P, p.Vt, nullptr, p.O,
        nullptr, nullptr, 0, -1, KT, NP, NP, Dn, 1.f, sS, sXD, sXD);
    // fused output projection (local row r -> out row r / aux at mtok)
    tgemm<3, true><<<dim3(8, 16, Bn), 256, TG_SMEM>>>(p.O, p.WoT, outp, nullptr,
        bo, aux, tokens, mtok, Dn, Dn, Dn, Dn, 1.f, sXD, 0,
        (long long)tokens * Dn);
}

extern "C" void kernel_launch(void* const* d_in, const int* in_sizes, int n_in,
                              void* d_out, int out_size)
{
    const float* seg0   = (const float*)d_in[0];
    const float* seg1   = (const float*)d_in[1];
    const float* pe     = (const float*)d_in[2];
    const float* Wq_mem = (const float*)d_in[3];
    const float* bq_mem = (const float*)d_in[4];
    const float* Wk_mem = (const float*)d_in[5];
    const float* bk_mem = (const float*)d_in[6];
    const float* Wq     = (const float*)d_in[7];
    const float* bq     = (const float*)d_in[8];
    const float* Wk     = (const float*)d_in[9];
    const float* bk     = (const float*)d_in[10];
    const float* Wv     = (const float*)d_in[11];
    const float* bv     = (const float*)d_in[12];
    const float* Wo     = (const float*)d_in[13];
    const float* bo     = (const float*)d_in[14];
    float* out = (float*)d_out;

    cudaFuncSetAttribute(tgemm<0, false>, cudaFuncAttributeMaxDynamicSharedMemorySize, TG_SMEM);
    cudaFuncSetAttribute(tgemm<1, false>, cudaFuncAttributeMaxDynamicSharedMemorySize, TG_SMEM);
    cudaFuncSetAttribute(tgemm<1, true>,  cudaFuncAttributeMaxDynamicSharedMemorySize, TG_SMEM);
    cudaFuncSetAttribute(tgemm<2, true>,  cudaFuncAttributeMaxDynamicSharedMemorySize, TG_SMEM);
    cudaFuncSetAttribute(tgemm<3, true>,  cudaFuncAttributeMaxDynamicSharedMemorySize, TG_SMEM);

    Ptrs p;
    cudaGetSymbolAddress((void**)&p.X, g_X);
    cudaGetSymbolAddress((void**)&p.Q, g_Q);
    cudaGetSymbolAddress((void**)&p.K, g_K);
    cudaGetSymbolAddress((void**)&p.Vt, g_Vt);
    cudaGetSymbolAddress((void**)&p.O, g_O);
    cudaGetSymbolAddress((void**)&p.P, g_P);
    cudaGetSymbolAddress((void**)&p.WqT, g_WqT);
    cudaGetSymbolAddress((void**)&p.WkT, g_WkT);
    cudaGetSymbolAddress((void**)&p.WvT, g_WvT);
    cudaGetSymbolAddress((void**)&p.WoT, g_WoT);
    cudaGetSymbolAddress((void**)&p.S, g_S);
    cudaGetSymbolAddress((void**)&p.M1, g_M1);
    cudaGetSymbolAddress((void**)&p.S1, g_S1);
    cudaGetSymbolAddress((void**)&p.Qn, g_Qn);
    cudaGetSymbolAddress((void**)&p.Kp, g_Kp);
    cudaGetSymbolAddress((void**)&p.P1, g_P1);

    dim3 wg(32, 32), wb(32, 8);
    wcvt_t<<<wg, wb>>>(Wq, p.WqT);
    wcvt_t<<<wg, wb>>>(Wk, p.WkT);
    wcvt_t<<<wg, wb>>>(Wv, p.WvT);
    wcvt_t<<<wg, wb>>>(Wo, p.WoT);

    // ---- Stage A: backbone over input_h0 (n = 2050) ----
    // out0 = local rows 0..2015 (global 33..2048); M1 = local row 2016 (2049).
    build_x0h<<<dim3(NP * Dn / 512, Bn), 256>>>(seg0, p.X);
    run_backbone_full(p, bq, bk, bv, bo, 2050, out, 2016, 2016, p.M1);

    // ---- Stage B: summarize(seg1) (n = 514) ----
    // Only output token 512 is needed -> single 128-row M-tile [512, 640).
    {
        const long long sXD = (long long)NS * Dn;
        const long long sPP = (long long)NS * NS;
        build_xsh<<<dim3(NS * Dn / 512, Bn), 256>>>(seg1, pe, p.X);
        tgemm<1, true><<<dim3(8, 5, Bn), 256, TG_SMEM>>>(p.X, p.WkT, nullptr,
            p.K, bk, nullptr, 0, -1, Dn, Dn, Dn, Dn, 1.f, sXD, 0, sXD);
        tgemm<2, true><<<dim3(8, 5, Bn), 256, TG_SMEM>>>(p.X, p.WvT, nullptr,
            p.Vt, bv, nullptr, 0, -1, Dn, Dn, Dn, NS, 1.f, sXD, 0, sXD);
        tgemm<1, true><<<dim3(8, 1, Bn), 256, TG_SMEM>>>(p.X + 512 * Dn, p.WqT,
            nullptr, p.Q + 512 * Dn, bq, nullptr, 0, -1,
            Dn, Dn, Dn, Dn, 1.f, sXD, 0, sXD);
        tgemm<0, false><<<dim3(5, 1, Bn), 256, TG_SMEM>>>(p.Q + 512 * Dn, p.K,
            p.S + 512 * NS, nullptr, nullptr, nullptr, 0, -1,
            Dn, Dn, Dn, NS, 0.03125f, sXD, sXD, sPP);
        softmax_reg<<<dim3(128, Bn), 256>>>(p.S, p.P, 514, NS, NS, 512);
        tgemm<1, false><<<dim3(8, 1, Bn), 256, TG_SMEM>>>(p.P + 512 * NS, p.Vt,
            nullptr, p.O + 512 * Dn, nullptr, nullptr, 0, -1,
            576, NS, NS, Dn, 1.f, sPP, sXD, sXD);
        // O-proj: local row 0 (= token 512) -> S1; no out writes (tokens=0)
        tgemm<3, true><<<dim3(8, 1, Bn), 256, TG_SMEM>>>(p.O + 512 * Dn, p.WoT,
            out, nullptr, bo, p.S1, 0, 0, Dn, Dn, Dn, Dn, 1.f, sXD, 0, 0);
    }

    // ---- Stage C: memory attention (tiny, fp32 path) ----
    dim3 gMem(Dn / 128, 1, 1);
    sgemm<false, true><<<gMem, 256>>>(p.S1, Wq_mem, p.Qn, bq_mem, Dn, Dn, 1.f);
    sgemm<false, true><<<gMem, 256>>>(p.M1, Wk_mem, p.Kp, bk_mem, Dn, Dn, 1.f);
    mem_attn<<<Bn, 256>>>(p.Qn, p.Kp, p.M1, p.P1);

    // ---- Stage D: backbone over input_h1 (n = 2082) ----
    // out1 = local rows 0..2047 (global 33..2080); no summary token.
    build_x1h<<<dim3(NP * Dn / 512, Bn), 256>>>(seg0, seg1, p.P1, p.X);
    run_backbone_full(p, bq, bk, bv, bo, 2082,
                      out + (long long)Bn * 2016 * Dn, 2048, -1, p.M1);
}

// round 11
// speedup vs baseline: 1.2170x; 1.0495x over previous
#include <cuda_runtime.h>
#include <cuda_fp16.h>
#include <math.h>
#include <cstdint>

// ---------------------------------------------------------------------------
// Problem constants: B=8, L=2048, D=1024, K=32, J=512
//   backbone0 n=2050, summarize n=514, backbone1 n=2082
//   Pad to NP=2176 (17*128) and NS=640 (5*128).
//   Stages A/D: query rows offset by 33 -> 2048 rows = 16 M-tiles.
//   Stage B runs CONCURRENTLY with stage A on a second stream (fork-join
//   capture pattern) using its own scratch buffers.
// ---------------------------------------------------------------------------
#define Bn 8
#define Dn 1024
#define NP 2176
#define NS 640
#define MQ 2048   // query rows per batch in stages A/D (local row = global-33)

#define EL_XD ((size_t)Bn * NP * Dn)
#define EL_PP ((size_t)Bn * NP * NP)
#define EL_XS ((size_t)Bn * NS * Dn)
#define EL_SS ((size_t)Bn * NS * NS)

// Stage A/D scratch
__device__ __align__(256) __half g_X[EL_XD];
__device__ __align__(256) __half g_Q[EL_XD];
__device__ __align__(256) __half g_K[EL_XD];
__device__ __align__(256) __half g_Vt[EL_XD];   // V transposed [d][token]
__device__ __align__(256) __half g_O[EL_XD];
__device__ __align__(256) __half g_P[EL_PP];
__device__ __align__(256) float  g_S[EL_PP];
// Stage B scratch (separate so B can overlap A)
__device__ __align__(256) __half g_XB[EL_XS];
__device__ __align__(256) __half g_QB[EL_XS];
__device__ __align__(256) __half g_KB[EL_XS];
__device__ __align__(256) __half g_VtB[EL_XS];
__device__ __align__(256) __half g_OB[EL_XS];
__device__ __align__(256) __half g_PB[EL_SS];
__device__ __align__(256) float  g_SB[EL_SS];
// weights
__device__ __align__(256) __half g_WqT[Dn*Dn], g_WkT[Dn*Dn], g_WvT[Dn*Dn], g_WoT[Dn*Dn];
// stage C fp32 scratch. g_M1/g_S1 rows 8..127 are NEVER written -> stay zero.
__device__ __align__(256) float g_M1[128 * Dn];
__device__ __align__(256) float g_S1[128 * Dn];
__device__ __align__(256) float g_Qn[128 * Dn];
__device__ __align__(256) float g_Kp[128 * Dn];
__device__ __align__(256) float g_P1[Bn * Dn];

// ---------------------------------------------------------------------------
// helpers
// ---------------------------------------------------------------------------
__device__ __forceinline__ uint32_t smem_u32(const void* p) {
    uint32_t a;
    asm("{ .reg .u64 t; cvta.to.shared.u64 t, %1; cvt.u32.u64 %0, t; }"
        : "=r"(a) : "l"(p));
    return a;
}
// SW128 swizzle for [row][64 half] tiles (128B rows): 16B chunk col XOR row%8
__device__ __forceinline__ uint32_t swz(int row, int col16) {
    return ((uint32_t)row << 7) | ((uint32_t)((col16 ^ row) & 7) << 4);
}
__device__ __forceinline__ void ldsm4(uint32_t* r, uint32_t addr) {
    asm volatile("ldmatrix.sync.aligned.m8n8.x4.shared.b16 {%0,%1,%2,%3}, [%4];"
        : "=r"(r[0]), "=r"(r[1]), "=r"(r[2]), "=r"(r[3]) : "r"(addr));
}
__device__ __forceinline__ void mma_f16(float* d, const uint32_t* a, const uint32_t* b) {
    asm volatile(
        "mma.sync.aligned.m16n8k16.row.col.f32.f16.f16.f32 "
        "{%0,%1,%2,%3}, {%4,%5,%6,%7}, {%8,%9}, {%0,%1,%2,%3};"
        : "+f"(d[0]), "+f"(d[1]), "+f"(d[2]), "+f"(d[3])
        : "r"(a[0]), "r"(a[1]), "r"(a[2]), "r"(a[3]), "r"(b[0]), "r"(b[1]));
}

// ---------------------------------------------------------------------------
// fp16 tensor-core GEMM: C = scale * A * B^T (+bias over cols)
//   MODE 0: fp32 out; MODE 1: fp16 out; MODE 2: fp16 TRANSPOSED out
//   MODE 3: fused fp32 output epilogue — local row r: r < tokens -> Cf row r;
//           r == mtok -> aux[z*1024 + col]; others discarded.
//   CTA tile 128x128, warp tile 64x32, K-chunk 64, 3-stage cp.async ring.
// ---------------------------------------------------------------------------
#define STAGE_B 32768            // A tile 16KB + B tile 16KB
#define TG_SMEM (3 * STAGE_B)    // 98304 bytes

__device__ __forceinline__ void fill_chunk(uint32_t sm,
    const __half* A, const __half* Bm, int ldA, int ldB, int t, int c)
{
    long long k0 = (long long)c << 6;
#pragma unroll
    for (int i = 0; i < 4; i++) {
        int seg = t + (i << 8);          // 0..1023 = row*8 + chunk
        int row = seg >> 3;
        int cc  = seg & 7;
        uint32_t so = swz(row, cc);
        asm volatile("cp.async.cg.shared.global [%0], [%1], 16;"
                     :: "r"(sm + so),
                        "l"(A + (long long)row * ldA + k0 + ((long long)cc << 3)));
        asm volatile("cp.async.cg.shared.global [%0], [%1], 16;"
                     :: "r"(sm + 16384u + so),
                        "l"(Bm + (long long)row * ldB + k0 + ((long long)cc << 3)));
    }
}

template <int MODE, bool BIAS>
__global__ void __launch_bounds__(256, 2)
tgemm(const __half* __restrict__ A, const __half* __restrict__ Bm,
      float* __restrict__ Cf, __half* __restrict__ Ch,
      const float* __restrict__ bias, float* __restrict__ aux,
      int tokens, int mtok,
      int Kd, int ldA, int ldB, int ldc, float scale,
      long long sA, long long sB, long long sC)
{
    extern __shared__ __align__(1024) char smem[];
    const int tid = threadIdx.x, wid = tid >> 5, lane = tid & 31;
    const long long z = blockIdx.z;
    A += z * sA; Bm += z * sB;
    if (MODE == 0 || MODE == 3) Cf += z * sC; else Ch += z * sC;

    const uint32_t sb = smem_u32(smem);
    const __half* At = A  + (long long)blockIdx.y * 128 * ldA;
    const __half* Bt = Bm + (long long)blockIdx.x * 128 * ldB;

    const int wr = wid >> 2, wc = wid & 3;    // 2 x 4 warp grid
    const int m0 = wr * 64, n0 = wc * 32;

    float acc[4][4][4];
#pragma unroll
    for (int i = 0; i < 4; i++)
#pragma unroll
        for (int j = 0; j < 4; j++)
#pragma unroll
            for (int r = 0; r < 4; r++) acc[i][j][r] = 0.f;

    const int NC = Kd >> 6;
    fill_chunk(sb, At, Bt, ldA, ldB, tid, 0);
    asm volatile("cp.async.commit_group;");
    if (NC > 1) {
        fill_chunk(sb + STAGE_B, At, Bt, ldA, ldB, tid, 1);
        asm volatile("cp.async.commit_group;");
    }

#pragma unroll 1
    for (int c = 0; c < NC; c++) {
        if (c == NC - 1) asm volatile("cp.async.wait_group 0;");
        else             asm volatile("cp.async.wait_group 1;");
        __syncthreads();

        const uint32_t tb = sb + (uint32_t)(c % 3) * STAGE_B;
        const uint32_t aA = tb, aB = tb + 16384u;

#pragma unroll
        for (int kk = 0; kk < 4; kk++) {
            const int k16 = kk << 1;  // 16B-chunk base of this 16-K step
            uint32_t Af[4][4], Bf[2][4];
            const int ar = m0 + (lane & 15);
            const int ac = k16 + (lane >> 4);
#pragma unroll
            for (int i = 0; i < 4; i++)
                ldsm4(Af[i], aA + swz(ar + 16 * i, ac));
            const int br = n0 + ((lane >> 4) << 3) + (lane & 7);
            const int bc = k16 + ((lane >> 3) & 1);
#pragma unroll
            for (int j2 = 0; j2 < 2; j2++)
                ldsm4(Bf[j2], aB + swz(br + 16 * j2, bc));
#pragma unroll
            for (int i = 0; i < 4; i++)
#pragma unroll
                for (int jt = 0; jt < 4; jt++)
                    mma_f16(acc[i][jt], Af[i], &Bf[jt >> 1][(jt & 1) << 1]);
        }
        if (c + 2 < NC) {
            fill_chunk(sb + (uint32_t)((c + 2) % 3) * STAGE_B, At, Bt, ldA, ldB,
                       tid, c + 2);
            asm volatile("cp.async.commit_group;");
        }
    }

    // ---------------- epilogue ----------------
    const int row0 = blockIdx.y * 128, col0 = blockIdx.x * 128;
    const int rl = lane >> 2;              // 0..7
    const int cl = (lane & 3) << 1;        // 0,2,4,6
#pragma unroll
    for (int i = 0; i < 4; i++) {
        const long long rg0 = row0 + m0 + i * 16 + rl;
        const long long rg1 = rg0 + 8;
#pragma unroll
        for (int j = 0; j < 4; j++) {
            const int cg = col0 + n0 + j * 8 + cl;
            float v00 = acc[i][j][0] * scale, v01 = acc[i][j][1] * scale;
            float v10 = acc[i][j][2] * scale, v11 = acc[i][j][3] * scale;
            if (BIAS) {
                const float b0 = bias[cg], b1 = bias[cg + 1];
                v00 += b0; v01 += b1; v10 += b0; v11 += b1;
            }
            if (MODE == 0) {
                *(float2*)(Cf + rg0 * ldc + cg) = make_float2(v00, v01);
                *(float2*)(Cf + rg1 * ldc + cg) = make_float2(v10, v11);
            } else if (MODE == 1) {
                *(__half2*)(Ch + rg0 * ldc + cg) =
                    __halves2half2(__float2half_rn(v00), __float2half_rn(v01));
                *(__half2*)(Ch + rg1 * ldc + cg) =
                    __halves2half2(__float2half_rn(v10), __float2half_rn(v11));
            } else if (MODE == 2) {
                Ch[(long long)cg * ldc + rg0]       = __float2half_rn(v00);
                Ch[(long long)(cg + 1) * ldc + rg0] = __float2half_rn(v01);
                Ch[(long long)cg * ldc + rg1]       = __float2half_rn(v10);
                Ch[(long long)(cg + 1) * ldc + rg1] = __float2half_rn(v11);
            } else {
                const int r0 = (int)rg0, r1 = (int)rg1;
                if (r0 < tokens)
                    *(float2*)(Cf + (long long)r0 * ldc + cg) =
                        make_float2(v00, v01);
                if (r0 == mtok)
                    *(float2*)(aux + z * 1024 + cg) = make_float2(v00, v01);
                if (r1 < tokens)
                    *(float2*)(Cf + (long long)r1 * ldc + cg) =
                        make_float2(v10, v11);
                if (r1 == mtok)
                    *(float2*)(aux + z * 1024 + cg) = make_float2(v10, v11);
            }
        }
    }
}

// ---------------------------------------------------------------------------
// Register-cached row softmax: ONE read of S, one exp, one fp16 write.
// Batch b's rows live at (b*rowsPB + row)*npad. Processes rows
// [row0, row0 + gridDim.x); cols >= n written as 0.
// ---------------------------------------------------------------------------
__global__ void softmax_reg(const float* __restrict__ S, __half* __restrict__ P,
                            int n, int npad, int rowsPB, int row0)
{
    const long long roff =
        ((long long)blockIdx.y * rowsPB + (row0 + blockIdx.x)) * npad;
    const float4* row4 = (const float4*)(S + roff);
    __half* pr = P + roff;
    const int t = threadIdx.x;
    const int npad4 = npad >> 2;
    __shared__ float red[256];

    float4 v[3];
    float m = -1e30f;
#pragma unroll
    for (int p = 0; p < 3; p++) {
        const int i4 = t + (p << 8);
        if (i4 < npad4) {
            v[p] = row4[i4];
            const int j = i4 << 2;
            if (j + 0 < n) m = fmaxf(m, v[p].x);
            if (j + 1 < n) m = fmaxf(m, v[p].y);
            if (j + 2 < n) m = fmaxf(m, v[p].z);
            if (j + 3 < n) m = fmaxf(m, v[p].w);
        }
    }
    red[t] = m; __syncthreads();
    for (int s = 128; s > 0; s >>= 1) {
        if (t < s) red[t] = fmaxf(red[t], red[t + s]);
        __syncthreads();
    }
    m = red[0]; __syncthreads();

    float sum = 0.f;
#pragma unroll
    for (int p = 0; p < 3; p++) {
        const int i4 = t + (p << 8);
        if (i4 < npad4) {
            const int j = i4 << 2;
            v[p].x = (j + 0 < n) ? __expf(v[p].x - m) : 0.f;
            v[p].y = (j + 1 < n) ? __expf(v[p].y - m) : 0.f;
            v[p].z = (j + 2 < n) ? __expf(v[p].z - m) : 0.f;
            v[p].w = (j + 3 < n) ? __expf(v[p].w - m) : 0.f;
            sum += v[p].x + v[p].y + v[p].z + v[p].w;
        }
    }
    red[t] = sum; __syncthreads();
    for (int s = 128; s > 0; s >>= 1) {
        if (t < s) red[t] += red[t + s];
        __syncthreads();
    }
    const float inv = 1.f / red[0];

#pragma unroll
    for (int p = 0; p < 3; p++) {
        const int i4 = t + (p << 8);
        if (i4 < npad4) {
            const int j = i4 << 2;
            *(__half2*)(pr + j)     = __halves2half2(__float2half_rn(v[p].x * inv),
                                                     __float2half_rn(v[p].y * inv));
            *(__half2*)(pr + j + 2) = __halves2half2(__float2half_rn(v[p].z * inv),
                                                     __float2half_rn(v[p].w * inv));
        }
    }
}

// ---------------------------------------------------------------------------
// Input assembly (fp32 -> fp16), 2 elems/thread (half2 stores)
// ---------------------------------------------------------------------------
__global__ void build_x0h(const float* __restrict__ seg0, __half* __restrict__ X)
{
    int b = blockIdx.y;
    long long i2 = (long long)blockIdx.x * 256 + threadIdx.x;   // over NP*Dn/2
    int pos = (int)(i2 >> 9), d = (int)((i2 & 511) << 1);
    float2 v = make_float2(0.f, 0.f);
    if (pos >= 1 && pos <= 2048)
        v = *(const float2*)(seg0 + ((long long)b * 2048 + (pos - 1)) * 1024 + d);
    *(__half2*)(X + (long long)b * NP * 1024 + (i2 << 1)) =
        __halves2half2(__float2half_rn(v.x), __float2half_rn(v.y));
}

__global__ void build_xsh(const float* __restrict__ seg1, const float* __restrict__ pe,
                          __half* __restrict__ X)
{
    int b = blockIdx.y;
    long long i2 = (long long)blockIdx.x * 256 + threadIdx.x;   // over NS*Dn/2
    int pos = (int)(i2 >> 9), d = (int)((i2 & 511) << 1);
    float2 v = make_float2(0.f, 0.f);
    if (pos == 0 || pos == 513) v = *(const float2*)(pe + d);
    else if (pos >= 1 && pos <= 512)
        v = *(const float2*)(seg1 + ((long long)b * 2048 + (pos - 1)) * 1024 + d);
    *(__half2*)(X + (long long)b * NS * 1024 + (i2 << 1)) =
        __halves2half2(__float2half_rn(v.x), __float2half_rn(v.y));
}

__global__ void build_x1h(const float* __restrict__ seg0, const float* __restrict__ seg1,
                          const float* __restrict__ P1, __half* __restrict__ X)
{
    int b = blockIdx.y;
    long long i2 = (long long)blockIdx.x * 256 + threadIdx.x;   // over NP*Dn/2
    int pos = (int)(i2 >> 9), d = (int)((i2 & 511) << 1);
    float2 v = make_float2(0.f, 0.f);
    if (pos < 32)
        v = *(const float2*)(seg0 + ((long long)b * 2048 + (2016 + pos)) * 1024 + d);
    else if (pos == 32 || pos == 2081)
        v = *(const float2*)(P1 + b * 1024 + d);
    else if (pos >= 33 && pos <= 2080)
        v = *(const float2*)(seg1 + ((long long)b * 2048 + (pos - 33)) * 1024 + d);
    *(__half2*)(X + (long long)b * NP * 1024 + (i2 << 1)) =
        __halves2half2(__float2half_rn(v.x), __float2half_rn(v.y));
}

// smem-tiled weight transpose + convert: WT[n][k] = half(W[k][n])
__global__ void wcvt_t(const float* __restrict__ W, __half* __restrict__ WT)
{
    __shared__ float tile[32][33];
    const int k0 = blockIdx.y * 32, n0 = blockIdx.x * 32;
    for (int r = threadIdx.y; r < 32; r += 8)
        tile[r][threadIdx.x] = W[(long long)(k0 + r) * 1024 + n0 + threadIdx.x];
    __syncthreads();
    for (int r = threadIdx.y; r < 32; r += 8)
        WT[(long long)(n0 + r) * 1024 + k0 + threadIdx.x] =
            __float2half_rn(tile[threadIdx.x][r]);
}

// ---------------------------------------------------------------------------
// fp32 fallback SGEMM (stage C only; tiny)
// ---------------------------------------------------------------------------
template <bool TRANSB, bool BIAS>
__global__ void __launch_bounds__(256)
sgemm(const float* __restrict__ A, const float* __restrict__ Bm,
      float* __restrict__ C, const float* __restrict__ bias,
      int N, int Kd, float scale)
{
    __shared__ float As[8][128];
    __shared__ float Bs[8][128];
    const int t = threadIdx.x, tx = t & 15, ty = t >> 4;
    const int row0 = blockIdx.y * 128, col0 = blockIdx.x * 128;
    const int aRow = t >> 1, aCol = (t & 1) << 2;
    const int bRow = t >> 5, bCol = (t & 31) << 2;
    float acc[8][8];
#pragma unroll
    for (int i = 0; i < 8; i++)
#pragma unroll
        for (int j = 0; j < 8; j++) acc[i][j] = 0.f;
    const float* Aptr = A + (long long)(row0 + aRow) * Kd + aCol;
    const float* Bptr = TRANSB ? (Bm + (long long)(col0 + aRow) * Kd + aCol)
                               : (Bm + (long long)bRow * N + col0 + bCol);
    for (int k0 = 0; k0 < Kd; k0 += 8) {
        float4 av = *(const float4*)(Aptr + k0);
        As[aCol + 0][aRow] = av.x; As[aCol + 1][aRow] = av.y;
        As[aCol + 2][aRow] = av.z; As[aCol + 3][aRow] = av.w;
        if (TRANSB) {
            float4 bv = *(const float4*)(Bptr + k0);
            Bs[aCol + 0][aRow] = bv.x; Bs[aCol + 1][aRow] = bv.y;
            Bs[aCol + 2][aRow] = bv.z; Bs[aCol + 3][aRow] = bv.w;
        } else {
            float4 bv = *(const float4*)(Bptr + (long long)k0 * N);
            *(float4*)&Bs[bRow][bCol] = bv;
        }
        __syncthreads();
#pragma unroll
        for (int kk = 0; kk < 8; kk++) {
            float ar[8], br[8];
            *(float4*)&ar[0] = *(const float4*)&As[kk][ty * 8];
            *(float4*)&ar[4] = *(const float4*)&As[kk][ty * 8 + 4];
            *(float4*)&br[0] = *(const float4*)&Bs[kk][tx * 8];
            *(float4*)&br[4] = *(const float4*)&Bs[kk][tx * 8 + 4];
#pragma unroll
            for (int i = 0; i < 8; i++)
#pragma unroll
                for (int j = 0; j < 8; j++)
                    acc[i][j] = fmaf(ar[i], br[j], acc[i][j]);
        }
        __syncthreads();
    }
#pragma unroll
    for (int i = 0; i < 8; i++) {
        long long r = row0 + ty * 8 + i;
#pragma unroll
        for (int j = 0; j < 8; j += 4) {
            int c = col0 + tx * 8 + j;
            float4 v;
            v.x = acc[i][j + 0] * scale; v.y = acc[i][j + 1] * scale;
            v.z = acc[i][j + 2] * scale; v.w = acc[i][j + 3] * scale;
            if (BIAS) { v.x += bias[c]; v.y += bias[c + 1]; v.z += bias[c + 2]; v.w += bias[c + 3]; }
            *(float4*)(C + r * N + c) = v;
        }
    }
}

// Tiny 8-way memory attention
__global__ void mem_attn(const float* __restrict__ Qn, const float* __restrict__ Kp,
                         const float* __restrict__ M1, float* __restrict__ P1)
{
    int b = blockIdx.x, t = threadIdx.x;
    __shared__ float red[256];
    __shared__ float attn[Bn];
    for (int j = 0; j < Bn; j++) {
        float p = 0.f;
        for (int d = t; d < 1024; d += 256)
            p += Qn[b * 1024 + d] * Kp[j * 1024 + d];
        red[t] = p; __syncthreads();
        for (int s = 128; s > 0; s >>= 1) {
            if (t < s) red[t] += red[t + s];
            __syncthreads();
        }
        if (t == 0) attn[j] = red[0] * 0.03125f;
        __syncthreads();
    }
    if (t == 0) {
        float m = -1e30f;
        for (int j = 0; j < Bn; j++) m = fmaxf(m, attn[j]);
        float s = 0.f;
        for (int j = 0; j < Bn; j++) { attn[j] = __expf(attn[j] - m); s += attn[j]; }
        float inv = 1.f / s;
        for (int j = 0; j < Bn; j++) attn[j] *= inv;
    }
    __syncthreads();
    for (int d = t; d < 1024; d += 256) {
        float v = 0.f;
#pragma unroll
        for (int j = 0; j < Bn; j++) v += attn[j] * M1[j * 1024 + d];
        P1[b * 1024 + d] = v;
    }
}

// ---------------------------------------------------------------------------
// Host orchestration
// ---------------------------------------------------------------------------
struct Ptrs {
    __half *X, *Q, *K, *Vt, *O, *P;
    __half *XB, *QB, *KB, *VtB, *OB, *PB;
    __half *WqT, *WkT, *WvT, *WoT;
    float *S, *SB, *M1, *S1, *Qn, *Kp, *P1;
};

// Full backbone (stages A/D) on the given stream. Query side = MQ rows
// (global [33, 2081)); O-proj writes outp rows [0, tokens) + aux at mtok.
static void run_backbone_full(const Ptrs& p, cudaStream_t st,
                              const float* bq, const float* bk,
                              const float* bv, const float* bo,
                              int n, float* outp, int tokens, int mtok,
                              float* aux)
{
    const long long sXD = (long long)NP * Dn;
    const long long sS  = (long long)MQ * NP;   // S/P per-batch stride
    const int KT = ((n + 63) / 64) * 64;
    tgemm<1, true><<<dim3(8, 17, Bn), 256, TG_SMEM, st>>>(p.X, p.WkT, nullptr,
        p.K, bk, nullptr, 0, -1, Dn, Dn, Dn, Dn, 1.f, sXD, 0, sXD);
    tgemm<2, true><<<dim3(8, 17, Bn), 256, TG_SMEM, st>>>(p.X, p.WvT, nullptr,
        p.Vt, bv, nullptr, 0, -1, Dn, Dn, Dn, NP, 1.f, sXD, 0, sXD);
    tgemm<1, true><<<dim3(8, 16, Bn), 256, TG_SMEM, st>>>(p.X + 33 * Dn, p.WqT,
        nullptr, p.Q, bq, nullptr, 0, -1, Dn, Dn, Dn, Dn, 1.f, sXD, 0, sXD);
    tgemm<0, false><<<dim3(17, 16, Bn), 256, TG_SMEM, st>>>(p.Q, p.K, p.S,
        nullptr, nullptr, nullptr, 0, -1, Dn, Dn, Dn, NP, 0.03125f,
        sXD, sXD, sS);
    softmax_reg<<<dim3(MQ, Bn), 256, 0, st>>>(p.S, p.P, n, NP, MQ, 0);
    tgemm<1, false><<<dim3(8, 16, Bn), 256, TG_SMEM, st>>>(p.P, p.Vt, nullptr,
        p.O, nullptr, nullptr, 0, -1, KT, NP, NP, Dn, 1.f, sS, sXD, sXD);
    tgemm<3, true><<<dim3(8, 16, Bn), 256, TG_SMEM, st>>>(p.O, p.WoT, outp,
        nullptr, bo, aux, tokens, mtok, Dn, Dn, Dn, Dn, 1.f, sXD, 0,
        (long long)tokens * Dn);
}

extern "C" void kernel_launch(void* const* d_in, const int* in_sizes, int n_in,
                              void* d_out, int out_size)
{
    const float* seg0   = (const float*)d_in[0];
    const float* seg1   = (const float*)d_in[1];
    const float* pe     = (const float*)d_in[2];
    const float* Wq_mem = (const float*)d_in[3];
    const float* bq_mem = (const float*)d_in[4];
    const float* Wk_mem = (const float*)d_in[5];
    const float* bk_mem = (const float*)d_in[6];
    const float* Wq     = (const float*)d_in[7];
    const float* bq     = (const float*)d_in[8];
    const float* Wk     = (const float*)d_in[9];
    const float* bk     = (const float*)d_in[10];
    const float* Wv     = (const float*)d_in[11];
    const float* bv     = (const float*)d_in[12];
    const float* Wo     = (const float*)d_in[13];
    const float* bo     = (const float*)d_in[14];
    float* out = (float*)d_out;

    // One-time host resources (persist across calls; destroying a stream that
    // participated in an in-progress capture is illegal, so never destroyed).
    static cudaStream_t s2 = nullptr;
    static cudaEvent_t evFork = nullptr, evJoin = nullptr;
    if (s2 == nullptr) {
        cudaStreamCreateWithFlags(&s2, cudaStreamNonBlocking);
        cudaEventCreateWithFlags(&evFork, cudaEventDisableTiming);
        cudaEventCreateWithFlags(&evJoin, cudaEventDisableTiming);
        cudaFuncSetAttribute(tgemm<0, false>, cudaFuncAttributeMaxDynamicSharedMemorySize, TG_SMEM);
        cudaFuncSetAttribute(tgemm<1, false>, cudaFuncAttributeMaxDynamicSharedMemorySize, TG_SMEM);
        cudaFuncSetAttribute(tgemm<1, true>,  cudaFuncAttributeMaxDynamicSharedMemorySize, TG_SMEM);
        cudaFuncSetAttribute(tgemm<2, true>,  cudaFuncAttributeMaxDynamicSharedMemorySize, TG_SMEM);
        cudaFuncSetAttribute(tgemm<3, true>,  cudaFuncAttributeMaxDynamicSharedMemorySize, TG_SMEM);
    }

    Ptrs p;
    cudaGetSymbolAddress((void**)&p.X, g_X);
    cudaGetSymbolAddress((void**)&p.Q, g_Q);
    cudaGetSymbolAddress((void**)&p.K, g_K);
    cudaGetSymbolAddress((void**)&p.Vt, g_Vt);
    cudaGetSymbolAddress((void**)&p.O, g_O);
    cudaGetSymbolAddress((void**)&p.P, g_P);
    cudaGetSymbolAddress((void**)&p.XB, g_XB);
    cudaGetSymbolAddress((void**)&p.QB, g_QB);
    cudaGetSymbolAddress((void**)&p.KB, g_KB);
    cudaGetSymbolAddress((void**)&p.VtB, g_VtB);
    cudaGetSymbolAddress((void**)&p.OB, g_OB);
    cudaGetSymbolAddress((void**)&p.PB, g_PB);
    cudaGetSymbolAddress((void**)&p.WqT, g_WqT);
    cudaGetSymbolAddress((void**)&p.WkT, g_WkT);
    cudaGetSymbolAddress((void**)&p.WvT, g_WvT);
    cudaGetSymbolAddress((void**)&p.WoT, g_WoT);
    cudaGetSymbolAddress((void**)&p.S, g_S);
    cudaGetSymbolAddress((void**)&p.SB, g_SB);
    cudaGetSymbolAddress((void**)&p.M1, g_M1);
    cudaGetSymbolAddress((void**)&p.S1, g_S1);
    cudaGetSymbolAddress((void**)&p.Qn, g_Qn);
    cudaGetSymbolAddress((void**)&p.Kp, g_Kp);
    cudaGetSymbolAddress((void**)&p.P1, g_P1);

    // ---- weight prep (main stream) ----
    dim3 wg(32, 32), wb(32, 8);
    wcvt_t<<<wg, wb>>>(Wq, p.WqT);
    wcvt_t<<<wg, wb>>>(Wk, p.WkT);
    wcvt_t<<<wg, wb>>>(Wv, p.WvT);
    wcvt_t<<<wg, wb>>>(Wo, p.WoT);

    // ---- FORK: stage B (summarize) runs on s2, concurrent with stage A ----
    cudaEventRecord(evFork, 0);
    cudaStreamWaitEvent(s2, evFork, 0);
    {
        const long long sXD = (long long)NS * Dn;
        const long long sPP = (long long)NS * NS;
        build_xsh<<<dim3(NS * Dn / 512, Bn), 256, 0, s2>>>(seg1, pe, p.XB);
        tgemm<1, true><<<dim3(8, 5, Bn), 256, TG_SMEM, s2>>>(p.XB, p.WkT,
            nullptr, p.KB, bk, nullptr, 0, -1, Dn, Dn, Dn, Dn, 1.f, sXD, 0, sXD);
        tgemm<2, true><<<dim3(8, 5, Bn), 256, TG_SMEM, s2>>>(p.XB, p.WvT,
            nullptr, p.VtB, bv, nullptr, 0, -1, Dn, Dn, Dn, NS, 1.f, sXD, 0, sXD);
        tgemm<1, true><<<dim3(8, 1, Bn), 256, TG_SMEM, s2>>>(p.XB + 512 * Dn,
            p.WqT, nullptr, p.QB + 512 * Dn, bq, nullptr, 0, -1,
            Dn, Dn, Dn, Dn, 1.f, sXD, 0, sXD);
        tgemm<0, false><<<dim3(5, 1, Bn), 256, TG_SMEM, s2>>>(p.QB + 512 * Dn,
            p.KB, p.SB + 512 * NS, nullptr, nullptr, nullptr, 0, -1,
            Dn, Dn, Dn, NS, 0.03125f, sXD, sXD, sPP);
        softmax_reg<<<dim3(128, Bn), 256, 0, s2>>>(p.SB, p.PB, 514, NS, NS, 512);
        tgemm<1, false><<<dim3(8, 1, Bn), 256, TG_SMEM, s2>>>(p.PB + 512 * NS,
            p.VtB, nullptr, p.OB + 512 * Dn, nullptr, nullptr, 0, -1,
            576, NS, NS, Dn, 1.f, sPP, sXD, sXD);
        // O-proj: local row 0 (= token 512) -> S1; no out writes (tokens=0)
        tgemm<3, true><<<dim3(8, 1, Bn), 256, TG_SMEM, s2>>>(p.OB + 512 * Dn,
            p.WoT, out, nullptr, bo, p.S1, 0, 0, Dn, Dn, Dn, Dn, 1.f,
            sXD, 0, 0);
        cudaEventRecord(evJoin, s2);
    }

    // ---- Stage A: backbone over input_h0 (n = 2050) on main stream ----
    build_x0h<<<dim3(NP * Dn / 512, Bn), 256>>>(seg0, p.X);
    run_backbone_full(p, 0, bq, bk, bv, bo, 2050, out, 2016, 2016, p.M1);

    // ---- JOIN: stage C needs S1 (from B) and M1 (from A) ----
    cudaStreamWaitEvent(0, evJoin, 0);
    dim3 gMem(Dn / 128, 1, 1);
    sgemm<false, true><<<gMem, 256>>>(p.S1, Wq_mem, p.Qn, bq_mem, Dn, Dn, 1.f);
    sgemm<false, true><<<gMem, 256>>>(p.M1, Wk_mem, p.Kp, bk_mem, Dn, Dn, 1.f);
    mem_attn<<<Bn, 256>>>(p.Qn, p.Kp, p.M1, p.P1);

    // ---- Stage D: backbone over input_h1 (n = 2082) on main stream ----
    build_x1h<<<dim3(NP * Dn / 512, Bn), 256>>>(seg0, seg1, p.P1, p.X);
    run_backbone_full(p, 0, bq, bk, bv, bo, 2082,
                      out + (long long)Bn * 2016 * Dn, 2048, -1, p.M1);
}

// round 12
// speedup vs baseline: 1.3503x; 1.1096x over previous
#include <cuda_runtime.h>
#include <cuda_fp16.h>
#include <math.h>
#include <cstdint>

// ---------------------------------------------------------------------------
// Problem constants: B=8, L=2048, D=1024, K=32, J=512
//   backbone0 n=2050, summarize n=514, backbone1 n=2082
//   Pad to NP=2176 (17*128) and NS=640 (5*128).
//   Stages A/D: query rows offset by 33 -> 2048 rows = 16 M-tiles.
//   Stage B + stage C + stage-D input prep run on a second stream, overlapped
//   with stages A and D's P1-independent GEMMs.
// ---------------------------------------------------------------------------
#define Bn 8
#define Dn 1024
#define NP 2176
#define NS 640
#define MQ 2048   // query rows per batch in stages A/D (local row = global-33)

#define EL_XD ((size_t)Bn * NP * Dn)
#define EL_PP ((size_t)Bn * NP * NP)
#define EL_XS ((size_t)Bn * NS * Dn)
#define EL_SS ((size_t)Bn * NS * NS)

// Stage A/D scratch
__device__ __align__(256) __half g_X[EL_XD];     // stage A input
__device__ __align__(256) __half g_XD[EL_XD];    // stage D input (built early)
__device__ __align__(256) __half g_Q[EL_XD];
__device__ __align__(256) __half g_K[EL_XD];
__device__ __align__(256) __half g_Vt[EL_XD];    // V transposed [d][token]
__device__ __align__(256) __half g_O[EL_XD];
__device__ __align__(256) __half g_P[EL_PP];
__device__ __align__(256) float  g_S[EL_PP];
// Stage B scratch (separate so B can overlap A)
__device__ __align__(256) __half g_XB[EL_XS];
__device__ __align__(256) __half g_QB[EL_XS];
__device__ __align__(256) __half g_KB[EL_XS];
__device__ __align__(256) __half g_VtB[EL_XS];
__device__ __align__(256) __half g_OB[EL_XS];
__device__ __align__(256) __half g_PB[EL_SS];
__device__ __align__(256) float  g_SB[EL_SS];
// weights: WqT, WoT standalone; Wk/Wv concatenated for the merged KV GEMM
__device__ __align__(256) __half g_WqT[Dn*Dn], g_WoT[Dn*Dn];
__device__ __align__(256) __half g_WkvT[2*Dn*Dn];   // rows 0..1023 = WkT, 1024.. = WvT
// stage C fp32 scratch. g_M1/g_S1 rows 8..127 are NEVER written -> stay zero.
__device__ __align__(256) float g_M1[128 * Dn];
__device__ __align__(256) float g_S1[128 * Dn];
__device__ __align__(256) float g_Qn[128 * Dn];
__device__ __align__(256) float g_Kp[128 * Dn];
__device__ __align__(256) float g_P1[Bn * Dn];

// ---------------------------------------------------------------------------
// helpers
// ---------------------------------------------------------------------------
__device__ __forceinline__ uint32_t smem_u32(const void* p) {
    uint32_t a;
    asm("{ .reg .u64 t; cvta.to.shared.u64 t, %1; cvt.u32.u64 %0, t; }"
        : "=r"(a) : "l"(p));
    return a;
}
// SW128 swizzle for [row][64 half] tiles (128B rows): 16B chunk col XOR row%8
__device__ __forceinline__ uint32_t swz(int row, int col16) {
    return ((uint32_t)row << 7) | ((uint32_t)((col16 ^ row) & 7) << 4);
}
__device__ __forceinline__ void ldsm4(uint32_t* r, uint32_t addr) {
    asm volatile("ldmatrix.sync.aligned.m8n8.x4.shared.b16 {%0,%1,%2,%3}, [%4];"
        : "=r"(r[0]), "=r"(r[1]), "=r"(r[2]), "=r"(r[3]) : "r"(addr));
}
__device__ __forceinline__ void mma_f16(float* d, const uint32_t* a, const uint32_t* b) {
    asm volatile(
        "mma.sync.aligned.m16n8k16.row.col.f32.f16.f16.f32 "
        "{%0,%1,%2,%3}, {%4,%5,%6,%7}, {%8,%9}, {%0,%1,%2,%3};"
        : "+f"(d[0]), "+f"(d[1]), "+f"(d[2]), "+f"(d[3])
        : "r"(a[0]), "r"(a[1]), "r"(a[2]), "r"(a[3]), "r"(b[0]), "r"(b[1]));
}

// ---------------------------------------------------------------------------
// fp16 tensor-core GEMM: C = scale * A * B^T (+bias over cols)
//   MODE 0: fp32 out; MODE 1: fp16 out; MODE 2: fp16 TRANSPOSED out
//   MODE 3: fused fp32 output epilogue — local row r: r < tokens -> Cf row r;
//           r == mtok -> aux[z*1024 + col]; others discarded.
//   MODE 5: merged K/V projection — blockIdx.x < xsplit: fp16 out to Ch
//           (bias, ldc); else TRANSPOSED fp16 out to Ch2 (bias2, ldc2) with
//           column index rebased by xsplit*128.
//   CTA tile 128x128, warp tile 64x32, K-chunk 64, 3-stage cp.async ring.
// ---------------------------------------------------------------------------
#define STAGE_B 32768            // A tile 16KB + B tile 16KB
#define TG_SMEM (3 * STAGE_B)    // 98304 bytes

__device__ __forceinline__ void fill_chunk(uint32_t sm,
    const __half* A, const __half* Bm, int ldA, int ldB, int t, int c)
{
    long long k0 = (long long)c << 6;
#pragma unroll
    for (int i = 0; i < 4; i++) {
        int seg = t + (i << 8);          // 0..1023 = row*8 + chunk
        int row = seg >> 3;
        int cc  = seg & 7;
        uint32_t so = swz(row, cc);
        asm volatile("cp.async.cg.shared.global [%0], [%1], 16;"
                     :: "r"(sm + so),
                        "l"(A + (long long)row * ldA + k0 + ((long long)cc << 3)));
        asm volatile("cp.async.cg.shared.global [%0], [%1], 16;"
                     :: "r"(sm + 16384u + so),
                        "l"(Bm + (long long)row * ldB + k0 + ((long long)cc << 3)));
    }
}

template <int MODE, bool BIAS>
__global__ void __launch_bounds__(256, 2)
tgemm(const __half* __restrict__ A, const __half* __restrict__ Bm,
      float* __restrict__ Cf, __half* __restrict__ Ch, __half* __restrict__ Ch2,
      const float* __restrict__ bias, const float* __restrict__ bias2,
      float* __restrict__ aux,
      int tokens, int mtok, int xsplit,
      int Kd, int ldA, int ldB, int ldc, int ldc2, float scale,
      long long sA, long long sB, long long sC)
{
    extern __shared__ __align__(1024) char smem[];
    const int tid = threadIdx.x, wid = tid >> 5, lane = tid & 31;
    const long long z = blockIdx.z;
    A += z * sA; Bm += z * sB;
    if (MODE == 0 || MODE == 3) Cf += z * sC;
    else { Ch += z * sC; if (MODE == 5) Ch2 += z * sC; }

    const uint32_t sb = smem_u32(smem);
    const __half* At = A  + (long long)blockIdx.y * 128 * ldA;
    const __half* Bt = Bm + (long long)blockIdx.x * 128 * ldB;

    const int wr = wid >> 2, wc = wid & 3;    // 2 x 4 warp grid
    const int m0 = wr * 64, n0 = wc * 32;

    float acc[4][4][4];
#pragma unroll
    for (int i = 0; i < 4; i++)
#pragma unroll
        for (int j = 0; j < 4; j++)
#pragma unroll
            for (int r = 0; r < 4; r++) acc[i][j][r] = 0.f;

    const int NC = Kd >> 6;
    fill_chunk(sb, At, Bt, ldA, ldB, tid, 0);
    asm volatile("cp.async.commit_group;");
    if (NC > 1) {
        fill_chunk(sb + STAGE_B, At, Bt, ldA, ldB, tid, 1);
        asm volatile("cp.async.commit_group;");
    }

#pragma unroll 1
    for (int c = 0; c < NC; c++) {
        if (c == NC - 1) asm volatile("cp.async.wait_group 0;");
        else             asm volatile("cp.async.wait_group 1;");
        __syncthreads();

        const uint32_t tb = sb + (uint32_t)(c % 3) * STAGE_B;
        const uint32_t aA = tb, aB = tb + 16384u;

#pragma unroll
        for (int kk = 0; kk < 4; kk++) {
            const int k16 = kk << 1;  // 16B-chunk base of this 16-K step
            uint32_t Af[4][4], Bf[2][4];
            const int ar = m0 + (lane & 15);
            const int ac = k16 + (lane >> 4);
#pragma unroll
            for (int i = 0; i < 4; i++)
                ldsm4(Af[i], aA + swz(ar + 16 * i, ac));
            const int br = n0 + ((lane >> 4) << 3) + (lane & 7);
            const int bc = k16 + ((lane >> 3) & 1);
#pragma unroll
            for (int j2 = 0; j2 < 2; j2++)
                ldsm4(Bf[j2], aB + swz(br + 16 * j2, bc));
#pragma unroll
            for (int i = 0; i < 4; i++)
#pragma unroll
                for (int jt = 0; jt < 4; jt++)
                    mma_f16(acc[i][jt], Af[i], &Bf[jt >> 1][(jt & 1) << 1]);
        }
        if (c + 2 < NC) {
            fill_chunk(sb + (uint32_t)((c + 2) % 3) * STAGE_B, At, Bt, ldA, ldB,
                       tid, c + 2);
            asm volatile("cp.async.commit_group;");
        }
    }

    // ---------------- epilogue ----------------
    const int row0 = blockIdx.y * 128, col0 = blockIdx.x * 128;
    const int rl = lane >> 2;              // 0..7
    const int cl = (lane & 3) << 1;        // 0,2,4,6
    // bias source / column rebase for MODE 5's V half
    const float* bp = bias;
    int cof = 0;
    bool vpath = false;
    if (MODE == 5 && col0 >= (xsplit << 7)) {
        bp = bias2;
        cof = xsplit << 7;
        vpath = true;
    }
#pragma unroll
    for (int i = 0; i < 4; i++) {
        const long long rg0 = row0 + m0 + i * 16 + rl;
        const long long rg1 = rg0 + 8;
#pragma unroll
        for (int j = 0; j < 4; j++) {
            const int cg = col0 + n0 + j * 8 + cl;
            float v00 = acc[i][j][0] * scale, v01 = acc[i][j][1] * scale;
            float v10 = acc[i][j][2] * scale, v11 = acc[i][j][3] * scale;
            if (BIAS) {
                const float b0 = bp[cg - cof], b1 = bp[cg - cof + 1];
                v00 += b0; v01 += b1; v10 += b0; v11 += b1;
            }
            if (MODE == 0) {
                *(float2*)(Cf + rg0 * ldc + cg) = make_float2(v00, v01);
                *(float2*)(Cf + rg1 * ldc + cg) = make_float2(v10, v11);
            } else if (MODE == 1) {
                *(__half2*)(Ch + rg0 * ldc + cg) =
                    __halves2half2(__float2half_rn(v00), __float2half_rn(v01));
                *(__half2*)(Ch + rg1 * ldc + cg) =
                    __halves2half2(__float2half_rn(v10), __float2half_rn(v11));
            } else if (MODE == 2) {
                Ch[(long long)cg * ldc + rg0]       = __float2half_rn(v00);
                Ch[(long long)(cg + 1) * ldc + rg0] = __float2half_rn(v01);
                Ch[(long long)cg * ldc + rg1]       = __float2half_rn(v10);
                Ch[(long long)(cg + 1) * ldc + rg1] = __float2half_rn(v11);
            } else if (MODE == 3) {
                const int r0 = (int)rg0, r1 = (int)rg1;
                if (r0 < tokens)
                    *(float2*)(Cf + (long long)r0 * ldc + cg) =
                        make_float2(v00, v01);
                if (r0 == mtok)
                    *(float2*)(aux + z * 1024 + cg) = make_float2(v00, v01);
                if (r1 < tokens)
                    *(float2*)(Cf + (long long)r1 * ldc + cg) =
                        make_float2(v10, v11);
                if (r1 == mtok)
                    *(float2*)(aux + z * 1024 + cg) = make_float2(v10, v11);
            } else { // MODE 5
                if (!vpath) {
                    *(__half2*)(Ch + rg0 * ldc + cg) =
                        __halves2half2(__float2half_rn(v00), __float2half_rn(v01));
                    *(__half2*)(Ch + rg1 * ldc + cg) =
                        __halves2half2(__float2half_rn(v10), __float2half_rn(v11));
                } else {
                    const int vc = cg - cof;
                    Ch2[(long long)vc * ldc2 + rg0]       = __float2half_rn(v00);
                    Ch2[(long long)(vc + 1) * ldc2 + rg0] = __float2half_rn(v01);
                    Ch2[(long long)vc * ldc2 + rg1]       = __float2half_rn(v10);
                    Ch2[(long long)(vc + 1) * ldc2 + rg1] = __float2half_rn(v11);
                }
            }
        }
    }
}

// ---------------------------------------------------------------------------
// Register-cached row softmax: ONE read of S, one exp, one fp16 write.
// Batch b's rows live at (b*rowsPB + row)*npad. Processes rows
// [row0, row0 + gridDim.x); cols >= n written as 0.
// ---------------------------------------------------------------------------
__global__ void softmax_reg(const float* __restrict__ S, __half* __restrict__ P,
                            int n, int npad, int rowsPB, int row0)
{
    const long long roff =
        ((long long)blockIdx.y * rowsPB + (row0 + blockIdx.x)) * npad;
    const float4* row4 = (const float4*)(S + roff);
    __half* pr = P + roff;
    const int t = threadIdx.x;
    const int npad4 = npad >> 2;
    __shared__ float red[256];

    float4 v[3];
    float m = -1e30f;
#pragma unroll
    for (int p = 0; p < 3; p++) {
        const int i4 = t + (p << 8);
        if (i4 < npad4) {
            v[p] = row4[i4];
            const int j = i4 << 2;
            if (j + 0 < n) m = fmaxf(m, v[p].x);
            if (j + 1 < n) m = fmaxf(m, v[p].y);
            if (j + 2 < n) m = fmaxf(m, v[p].z);
            if (j + 3 < n) m = fmaxf(m, v[p].w);
        }
    }
    red[t] = m; __syncthreads();
    for (int s = 128; s > 0; s >>= 1) {
        if (t < s) red[t] = fmaxf(red[t], red[t + s]);
        __syncthreads();
    }
    m = red[0]; __syncthreads();

    float sum = 0.f;
#pragma unroll
    for (int p = 0; p < 3; p++) {
        const int i4 = t + (p << 8);
        if (i4 < npad4) {
            const int j = i4 << 2;
            v[p].x = (j + 0 < n) ? __expf(v[p].x - m) : 0.f;
            v[p].y = (j + 1 < n) ? __expf(v[p].y - m) : 0.f;
            v[p].z = (j + 2 < n) ? __expf(v[p].z - m) : 0.f;
            v[p].w = (j + 3 < n) ? __expf(v[p].w - m) : 0.f;
            sum += v[p].x + v[p].y + v[p].z + v[p].w;
        }
    }
    red[t] = sum; __syncthreads();
    for (int s = 128; s > 0; s >>= 1) {
        if (t < s) red[t] += red[t + s];
        __syncthreads();
    }
    const float inv = 1.f / red[0];

#pragma unroll
    for (int p = 0; p < 3; p++) {
        const int i4 = t + (p << 8);
        if (i4 < npad4) {
            const int j = i4 << 2;
            *(__half2*)(pr + j)     = __halves2half2(__float2half_rn(v[p].x * inv),
                                                     __float2half_rn(v[p].y * inv));
            *(__half2*)(pr + j + 2) = __halves2half2(__float2half_rn(v[p].z * inv),
                                                     __float2half_rn(v[p].w * inv));
        }
    }
}

// ---------------------------------------------------------------------------
// Input assembly (fp32 -> fp16), 2 elems/thread (half2 stores)
// ---------------------------------------------------------------------------
__global__ void build_x0h(const float* __restrict__ seg0, __half* __restrict__ X)
{
    int b = blockIdx.y;
    long long i2 = (long long)blockIdx.x * 256 + threadIdx.x;   // over NP*Dn/2
    int pos = (int)(i2 >> 9), d = (int)((i2 & 511) << 1);
    float2 v = make_float2(0.f, 0.f);
    if (pos >= 1 && pos <= 2048)
        v = *(const float2*)(seg0 + ((long long)b * 2048 + (pos - 1)) * 1024 + d);
    *(__half2*)(X + (long long)b * NP * 1024 + (i2 << 1)) =
        __halves2half2(__float2half_rn(v.x), __float2half_rn(v.y));
}

__global__ void build_xsh(const float* __restrict__ seg1, const float* __restrict__ pe,
                          __half* __restrict__ X)
{
    int b = blockIdx.y;
    long long i2 = (long long)blockIdx.x * 256 + threadIdx.x;   // over NS*Dn/2
    int pos = (int)(i2 >> 9), d = (int)((i2 & 511) << 1);
    float2 v = make_float2(0.f, 0.f);
    if (pos == 0 || pos == 513) v = *(const float2*)(pe + d);
    else if (pos >= 1 && pos <= 512)
        v = *(const float2*)(seg1 + ((long long)b * 2048 + (pos - 1)) * 1024 + d);
    *(__half2*)(X + (long long)b * NS * 1024 + (i2 << 1)) =
        __halves2half2(__float2half_rn(v.x), __float2half_rn(v.y));
}

// stage-D input, P1-independent part: rows 32 and 2081 written as ZERO,
// patched later by build_x1_p1 once P1 exists.
__global__ void build_x1main(const float* __restrict__ seg0,
                             const float* __restrict__ seg1,
                             __half* __restrict__ X)
{
    int b = blockIdx.y;
    long long i2 = (long long)blockIdx.x * 256 + threadIdx.x;   // over NP*Dn/2
    int pos = (int)(i2 >> 9), d = (int)((i2 & 511) << 1);
    float2 v = make_float2(0.f, 0.f);
    if (pos < 32)
        v = *(const float2*)(seg0 + ((long long)b * 2048 + (2016 + pos)) * 1024 + d);
    else if (pos >= 33 && pos <= 2080)
        v = *(const float2*)(seg1 + ((long long)b * 2048 + (pos - 33)) * 1024 + d);
    *(__half2*)(X + (long long)b * NP * 1024 + (i2 << 1)) =
        __halves2half2(__float2half_rn(v.x), __float2half_rn(v.y));
}

// patch rows 32 and 2081 with P1 (8 batches x 2 rows x 512 half2 = 8192)
__global__ void build_x1_p1(const float* __restrict__ P1, __half* __restrict__ X)
{
    int i = blockIdx.x * 256 + threadIdx.x;     // 0..8191
    int b = i >> 10;
    int rem = i & 1023;
    int pos = (rem >> 9) ? 2081 : 32;
    int d = (rem & 511) << 1;
    float2 v = *(const float2*)(P1 + b * 1024 + d);
    *(__half2*)(X + ((long long)b * NP + pos) * 1024 + d) =
        __halves2half2(__float2half_rn(v.x), __float2half_rn(v.y));
}

// smem-tiled weight transpose + convert: WT[n][k] = half(W[k][n])
__global__ void wcvt_t(const float* __restrict__ W, __half* __restrict__ WT)
{
    __shared__ float tile[32][33];
    const int k0 = blockIdx.y * 32, n0 = blockIdx.x * 32;
    for (int r = threadIdx.y; r < 32; r += 8)
        tile[r][threadIdx.x] = W[(long long)(k0 + r) * 1024 + n0 + threadIdx.x];
    __syncthreads();
    for (int r = threadIdx.y; r < 32; r += 8)
        WT[(long long)(n0 + r) * 1024 + k0 + threadIdx.x] =
            __float2half_rn(tile[threadIdx.x][r]);
}

// ---------------------------------------------------------------------------
// fp32 fallback SGEMM (stage C only; tiny)
// ---------------------------------------------------------------------------
template <bool TRANSB, bool BIAS>
__global__ void __launch_bounds__(256)
sgemm(const float* __restrict__ A, const float* __restrict__ Bm,
      float* __restrict__ C, const float* __restrict__ bias,
      int N, int Kd, float scale)
{
    __shared__ float As[8][128];
    __shared__ float Bs[8][128];
    const int t = threadIdx.x, tx = t & 15, ty = t >> 4;
    const int row0 = blockIdx.y * 128, col0 = blockIdx.x * 128;
    const int aRow = t >> 1, aCol = (t & 1) << 2;
    const int bRow = t >> 5, bCol = (t & 31) << 2;
    float acc[8][8];
#pragma unroll
    for (int i = 0; i < 8; i++)
#pragma unroll
        for (int j = 0; j < 8; j++) acc[i][j] = 0.f;
    const float* Aptr = A + (long long)(row0 + aRow) * Kd + aCol;
    const float* Bptr = TRANSB ? (Bm + (long long)(col0 + aRow) * Kd + aCol)
                               : (Bm + (long long)bRow * N + col0 + bCol);
    for (int k0 = 0; k0 < Kd; k0 += 8) {
        float4 av = *(const float4*)(Aptr + k0);
        As[aCol + 0][aRow] = av.x; As[aCol + 1][aRow] = av.y;
        As[aCol + 2][aRow] = av.z; As[aCol + 3][aRow] = av.w;
        if (TRANSB) {
            float4 bv = *(const float4*)(Bptr + k0);
            Bs[aCol + 0][aRow] = bv.x; Bs[aCol + 1][aRow] = bv.y;
            Bs[aCol + 2][aRow] = bv.z; Bs[aCol + 3][aRow] = bv.w;
        } else {
            float4 bv = *(const float4*)(Bptr + (long long)k0 * N);
            *(float4*)&Bs[bRow][bCol] = bv;
        }
        __syncthreads();
#pragma unroll
        for (int kk = 0; kk < 8; kk++) {
            float ar[8], br[8];
            *(float4*)&ar[0] = *(const float4*)&As[kk][ty * 8];
            *(float4*)&ar[4] = *(const float4*)&As[kk][ty * 8 + 4];
            *(float4*)&br[0] = *(const float4*)&Bs[kk][tx * 8];
            *(float4*)&br[4] = *(const float4*)&Bs[kk][tx * 8 + 4];
#pragma unroll
            for (int i = 0; i < 8; i++)
#pragma unroll
                for (int j = 0; j < 8; j++)
                    acc[i][j] = fmaf(ar[i], br[j], acc[i][j]);
        }
        __syncthreads();
    }
#pragma unroll
    for (int i = 0; i < 8; i++) {
        long long r = row0 + ty * 8 + i;
#pragma unroll
        for (int j = 0; j < 8; j += 4) {
            int c = col0 + tx * 8 + j;
            float4 v;
            v.x = acc[i][j + 0] * scale; v.y = acc[i][j + 1] * scale;
            v.z = acc[i][j + 2] * scale; v.w = acc[i][j + 3] * scale;
            if (BIAS) { v.x += bias[c]; v.y += bias[c + 1]; v.z += bias[c + 2]; v.w += bias[c + 3]; }
            *(float4*)(C + r * N + c) = v;
        }
    }
}

// Tiny 8-way memory attention
__global__ void mem_attn(const float* __restrict__ Qn, const float* __restrict__ Kp,
                         const float* __restrict__ M1, float* __restrict__ P1)
{
    int b = blockIdx.x, t = threadIdx.x;
    __shared__ float red[256];
    __shared__ float attn[Bn];
    for (int j = 0; j < Bn; j++) {
        float p = 0.f;
        for (int d = t; d < 1024; d += 256)
            p += Qn[b * 1024 + d] * Kp[j * 1024 + d];
        red[t] = p; __syncthreads();
        for (int s = 128; s > 0; s >>= 1) {
            if (t < s) red[t] += red[t + s];
            __syncthreads();
        }
        if (t == 0) attn[j] = red[0] * 0.03125f;
        __syncthreads();
    }
    if (t == 0) {
        float m = -1e30f;
        for (int j = 0; j < Bn; j++) m = fmaxf(m, attn[j]);
        float s = 0.f;
        for (int j = 0; j < Bn; j++) { attn[j] = __expf(attn[j] - m); s += attn[j]; }
        float inv = 1.f / s;
        for (int j = 0; j < Bn; j++) attn[j] *= inv;
    }
    __syncthreads();
    for (int d = t; d < 1024; d += 256) {
        float v = 0.f;
#pragma unroll
        for (int j = 0; j < Bn; j++) v += attn[j] * M1[j * 1024 + d];
        P1[b * 1024 + d] = v;
    }
}

// ---------------------------------------------------------------------------
// Host orchestration
// ---------------------------------------------------------------------------
extern "C" void kernel_launch(void* const* d_in, const int* in_sizes, int n_in,
                              void* d_out, int out_size)
{
    const float* seg0   = (const float*)d_in[0];
    const float* seg1   = (const float*)d_in[1];
    const float* pe     = (const float*)d_in[2];
    const float* Wq_mem = (const float*)d_in[3];
    const float* bq_mem = (const float*)d_in[4];
    const float* Wk_mem = (const float*)d_in[5];
    const float* bk_mem = (const float*)d_in[6];
    const float* Wq     = (const float*)d_in[7];
    const float* bq     = (const float*)d_in[8];
    const float* Wk     = (const float*)d_in[9];
    const float* bk     = (const float*)d_in[10];
    const float* Wv     = (const float*)d_in[11];
    const float* bv     = (const float*)d_in[12];
    const float* Wo     = (const float*)d_in[13];
    const float* bo     = (const float*)d_in[14];
    float* out = (float*)d_out;

    static cudaStream_t s2 = nullptr;
    static cudaEvent_t evFork = nullptr, evXD = nullptr, evA = nullptr, evC = nullptr;
    if (s2 == nullptr) {
        cudaStreamCreateWithFlags(&s2, cudaStreamNonBlocking);
        cudaEventCreateWithFlags(&evFork, cudaEventDisableTiming);
        cudaEventCreateWithFlags(&evXD, cudaEventDisableTiming);
        cudaEventCreateWithFlags(&evA, cudaEventDisableTiming);
        cudaEventCreateWithFlags(&evC, cudaEventDisableTiming);
        cudaFuncSetAttribute(tgemm<0, false>, cudaFuncAttributeMaxDynamicSharedMemorySize, TG_SMEM);
        cudaFuncSetAttribute(tgemm<1, false>, cudaFuncAttributeMaxDynamicSharedMemorySize, TG_SMEM);
        cudaFuncSetAttribute(tgemm<1, true>,  cudaFuncAttributeMaxDynamicSharedMemorySize, TG_SMEM);
        cudaFuncSetAttribute(tgemm<3, true>,  cudaFuncAttributeMaxDynamicSharedMemorySize, TG_SMEM);
        cudaFuncSetAttribute(tgemm<5, true>,  cudaFuncAttributeMaxDynamicSharedMemorySize, TG_SMEM);
    }

    __half *pX, *pXD, *pQ, *pK, *pVt, *pO, *pP;
    __half *pXB, *pQB, *pKB, *pVtB, *pOB, *pPB;
    __half *pWqT, *pWoT, *pWkvT;
    float *pS, *pSB, *pM1, *pS1, *pQn, *pKp, *pP1;
    cudaGetSymbolAddress((void**)&pX, g_X);
    cudaGetSymbolAddress((void**)&pXD, g_XD);
    cudaGetSymbolAddress((void**)&pQ, g_Q);
    cudaGetSymbolAddress((void**)&pK, g_K);
    cudaGetSymbolAddress((void**)&pVt, g_Vt);
    cudaGetSymbolAddress((void**)&pO, g_O);
    cudaGetSymbolAddress((void**)&pP, g_P);
    cudaGetSymbolAddress((void**)&pXB, g_XB);
    cudaGetSymbolAddress((void**)&pQB, g_QB);
    cudaGetSymbolAddress((void**)&pKB, g_KB);
    cudaGetSymbolAddress((void**)&pVtB, g_VtB);
    cudaGetSymbolAddress((void**)&pOB, g_OB);
    cudaGetSymbolAddress((void**)&pPB, g_PB);
    cudaGetSymbolAddress((void**)&pWqT, g_WqT);
    cudaGetSymbolAddress((void**)&pWoT, g_WoT);
    cudaGetSymbolAddress((void**)&pWkvT, g_WkvT);
    cudaGetSymbolAddress((void**)&pS, g_S);
    cudaGetSymbolAddress((void**)&pSB, g_SB);
    cudaGetSymbolAddress((void**)&pM1, g_M1);
    cudaGetSymbolAddress((void**)&pS1, g_S1);
    cudaGetSymbolAddress((void**)&pQn, g_Qn);
    cudaGetSymbolAddress((void**)&pKp, g_Kp);
    cudaGetSymbolAddress((void**)&pP1, g_P1);

    const long long sXD = (long long)NP * Dn;
    const long long sS  = (long long)MQ * NP;
    const long long sXB = (long long)NS * Dn;
    const long long sSB = (long long)NS * NS;

    // ---- weight prep (main stream) ----
    dim3 wg(32, 32), wb(32, 8);
    wcvt_t<<<wg, wb>>>(Wq, pWqT);
    wcvt_t<<<wg, wb>>>(Wk, pWkvT);
    wcvt_t<<<wg, wb>>>(Wv, pWkvT + (size_t)Dn * Dn);
    wcvt_t<<<wg, wb>>>(Wo, pWoT);

    // ---- FORK ----
    cudaEventRecord(evFork, 0);
    cudaStreamWaitEvent(s2, evFork, 0);

    // s2: stage-D input prep (P1-independent rows), then stage B, then Qn
    build_x1main<<<dim3(NP * Dn / 512, Bn), 256, 0, s2>>>(seg0, seg1, pXD);
    cudaEventRecord(evXD, s2);
    build_xsh<<<dim3(NS * Dn / 512, Bn), 256, 0, s2>>>(seg1, pe, pXB);
    // B: merged KV projection over all 5 tiles
    tgemm<5, true><<<dim3(16, 5, Bn), 256, TG_SMEM, s2>>>(pXB, pWkvT,
        nullptr, pKB, pVtB, bk, bv, nullptr, 0, -1, 8,
        Dn, Dn, Dn, Dn, NS, 1.f, sXB, 0, sXB);
    // B: Q projection rows 512..639
    tgemm<1, true><<<dim3(8, 1, Bn), 256, TG_SMEM, s2>>>(pXB + 512 * Dn, pWqT,
        nullptr, pQB + 512 * Dn, nullptr, bq, nullptr, nullptr, 0, -1, 0,
        Dn, Dn, Dn, Dn, 0, 1.f, sXB, 0, sXB);
    tgemm<0, false><<<dim3(5, 1, Bn), 256, TG_SMEM, s2>>>(pQB + 512 * Dn, pKB,
        pSB + 512 * NS, nullptr, nullptr, nullptr, nullptr, nullptr, 0, -1, 0,
        Dn, Dn, Dn, NS, 0, 0.03125f, sXB, sXB, sSB);
    softmax_reg<<<dim3(128, Bn), 256, 0, s2>>>(pSB, pPB, 514, NS, NS, 512);
    tgemm<1, false><<<dim3(8, 1, Bn), 256, TG_SMEM, s2>>>(pPB + 512 * NS, pVtB,
        nullptr, pOB + 512 * Dn, nullptr, nullptr, nullptr, nullptr, 0, -1, 0,
        576, NS, NS, Dn, 0, 1.f, sSB, sXB, sXB);
    tgemm<3, true><<<dim3(8, 1, Bn), 256, TG_SMEM, s2>>>(pOB + 512 * Dn, pWoT,
        out, nullptr, nullptr, bo, nullptr, pS1, 0, 0, 0,
        Dn, Dn, Dn, Dn, 0, 1.f, sXB, 0, 0);
    // Qn = S1 @ Wq_mem + bq_mem (S1 ready on s2)
    sgemm<false, true><<<dim3(Dn / 128, 1), 256, 0, s2>>>(pS1, Wq_mem, pQn,
                                                          bq_mem, Dn, Dn, 1.f);

    // ---- Stage A on main stream ----
    build_x0h<<<dim3(NP * Dn / 512, Bn), 256>>>(seg0, pX);
    {
        const int n = 2050, KT = ((n + 63) / 64) * 64;   // 2112
        tgemm<1, true><<<dim3(8, 16, Bn), 256, TG_SMEM>>>(pX + 33 * Dn, pWqT,
            nullptr, pQ, nullptr, bq, nullptr, nullptr, 0, -1, 0,
            Dn, Dn, Dn, Dn, 0, 1.f, sXD, 0, sXD);
        tgemm<5, true><<<dim3(16, 17, Bn), 256, TG_SMEM>>>(pX, pWkvT,
            nullptr, pK, pVt, bk, bv, nullptr, 0, -1, 8,
            Dn, Dn, Dn, Dn, NP, 1.f, sXD, 0, sXD);
        tgemm<0, false><<<dim3(17, 16, Bn), 256, TG_SMEM>>>(pQ, pK, pS,
            nullptr, nullptr, nullptr, nullptr, nullptr, 0, -1, 0,
            Dn, Dn, Dn, NP, 0, 0.03125f, sXD, sXD, sS);
        softmax_reg<<<dim3(MQ, Bn), 256>>>(pS, pP, n, NP, MQ, 0);
        tgemm<1, false><<<dim3(8, 16, Bn), 256, TG_SMEM>>>(pP, pVt,
            nullptr, pO, nullptr, nullptr, nullptr, nullptr, 0, -1, 0,
            KT, NP, NP, Dn, 0, 1.f, sS, sXD, sXD);
        tgemm<3, true><<<dim3(8, 16, Bn), 256, TG_SMEM>>>(pO, pWoT,
            out, nullptr, nullptr, bo, nullptr, pM1, 2016, 2016, 0,
            Dn, Dn, Dn, Dn, 0, 1.f, sXD, 0, (long long)2016 * Dn);
    }
    cudaEventRecord(evA, 0);

    // ---- s2: stage C (needs M1 from A) + P1 patch into XD ----
    cudaStreamWaitEvent(s2, evA, 0);
    sgemm<false, true><<<dim3(Dn / 128, 1), 256, 0, s2>>>(pM1, Wk_mem, pKp,
                                                          bk_mem, Dn, Dn, 1.f);
    mem_attn<<<Bn, 256, 0, s2>>>(pQn, pKp, pM1, pP1);
    build_x1_p1<<<32, 256, 0, s2>>>(pP1, pXD);
    cudaEventRecord(evC, s2);

    // ---- Stage D on main stream (P1-independent GEMMs overlap stage C) ----
    cudaStreamWaitEvent(0, evXD, 0);
    {
        const int n = 2082, KT = ((n + 63) / 64) * 64;   // 2112
        // Q projection: rows 33..2080, never touches P1 rows
        tgemm<1, true><<<dim3(8, 16, Bn), 256, TG_SMEM>>>(pXD + 33 * Dn, pWqT,
            nullptr, pQ, nullptr, bq, nullptr, nullptr, 0, -1, 0,
            Dn, Dn, Dn, Dn, 0, 1.f, sXD, 0, sXD);
        // merged KV, row-tiles 1..15 (no P1 rows)
        tgemm<5, true><<<dim3(16, 15, Bn), 256, TG_SMEM>>>(pXD + 128 * Dn,
            pWkvT, nullptr, pK + 128 * Dn, pVt + 128, bk, bv, nullptr,
            0, -1, 8, Dn, Dn, Dn, Dn, NP, 1.f, sXD, 0, sXD);
        // P1-dependent row-tiles 0 and 16 after stage C
        cudaStreamWaitEvent(0, evC, 0);
        tgemm<5, true><<<dim3(16, 1, Bn), 256, TG_SMEM>>>(pXD, pWkvT,
            nullptr, pK, pVt, bk, bv, nullptr, 0, -1, 8,
            Dn, Dn, Dn, Dn, NP, 1.f, sXD, 0, sXD);
        tgemm<5, true><<<dim3(16, 1, Bn), 256, TG_SMEM>>>(pXD + 2048 * Dn,
            pWkvT, nullptr, pK + 2048 * Dn, pVt + 2048, bk, bv, nullptr,
            0, -1, 8, Dn, Dn, Dn, Dn, NP, 1.f, sXD, 0, sXD);
        tgemm<0, false><<<dim3(17, 16, Bn), 256, TG_SMEM>>>(pQ, pK, pS,
            nullptr, nullptr, nullptr, nullptr, nullptr, 0, -1, 0,
            Dn, Dn, Dn, NP, 0, 0.03125f, sXD, sXD, sS);
        softmax_reg<<<dim3(MQ, Bn), 256>>>(pS, pP, n, NP, MQ, 0);
        tgemm<1, false><<<dim3(8, 16, Bn), 256, TG_SMEM>>>(pP, pVt,
            nullptr, pO, nullptr, nullptr, nullptr, nullptr, 0, -1, 0,
            KT, NP, NP, Dn, 0, 1.f, sS, sXD, sXD);
        tgemm<3, true><<<dim3(8, 16, Bn), 256, TG_SMEM>>>(pO, pWoT,
            out + (long long)Bn * 2016 * Dn, nullptr, nullptr, bo, nullptr,
            pM1, 2048, -1, 0, Dn, Dn, Dn, Dn, 0, 1.f, sXD, 0,
            (long long)2048 * Dn);
    }
}